// round 13
// baseline (speedup 1.0000x reference)
#include <cuda_runtime.h>
#include <stdint.h>

#define NMAX 200000
#define EMAX 400000
#define GMAX 8192
#define HMAX 256
#define BN_EPS 1e-5f

// ---------------- scratch (device globals: no allocation allowed) ----------
__device__ float g_dis[NMAX];
__device__ float g_hw[(size_t)NMAX * HMAX];    // activations buffer A
__device__ float g_agg[(size_t)NMAX * HMAX];   // activations buffer B
__device__ float g_a0[(size_t)NMAX * 9];
__device__ float g_colsum[HMAX];
__device__ float g_colsumsq[HMAX];
__device__ float g_scale[HMAX];
__device__ float g_shift[HMAX];
__device__ float g_pm[(size_t)GMAX * HMAX];
__device__ int g_rowcnt[NMAX];
__device__ int g_rowptr[NMAX + 1];
__device__ int g_fill[NMAX];
__device__ int g_esrc[EMAX];
__device__ int g_gcnt[GMAX];
__device__ int g_gptr[GMAX + 1];
__device__ int g_bsum[1024];
__device__ int g_boff[1024];
__device__ int g_dummy[4];

// ---------------- small utility kernels ------------------------------------
__global__ void k_zero_int(int* p, int n) {
    int i = blockIdx.x * blockDim.x + threadIdx.x;
    if (i < n) p[i] = 0;
}
__global__ void k_set_int(int* p, int v) { *p = v; }
__global__ void k_count(const int* __restrict__ idx, int* __restrict__ cnt, int n) {
    int i = blockIdx.x * blockDim.x + threadIdx.x;
    if (i < n) atomicAdd(&cnt[idx[i]], 1);
}
__global__ void k_dis(const int* __restrict__ cnt, float* __restrict__ dis, int n) {
    int i = blockIdx.x * blockDim.x + threadIdx.x;
    if (i < n) dis[i] = rsqrtf((float)cnt[i] + 1.0f);
}

// ---------------- 2-level exclusive scan (chunk = 1024) ---------------------
__global__ void k_scan1(const int* __restrict__ in, int n, int* __restrict__ out,
                        int* __restrict__ bsum) {
    __shared__ int sh[256];
    int t = threadIdx.x;
    int base = blockIdx.x * 1024 + t * 4;
    int v0 = (base + 0 < n) ? in[base + 0] : 0;
    int v1 = (base + 1 < n) ? in[base + 1] : 0;
    int v2 = (base + 2 < n) ? in[base + 2] : 0;
    int v3 = (base + 3 < n) ? in[base + 3] : 0;
    int s = v0 + v1 + v2 + v3;
    sh[t] = s;
    __syncthreads();
    for (int off = 1; off < 256; off <<= 1) {
        int x = (t >= off) ? sh[t - off] : 0;
        __syncthreads();
        sh[t] += x;
        __syncthreads();
    }
    int run = sh[t] - s;
    if (base + 0 < n) out[base + 0] = run; run += v0;
    if (base + 1 < n) out[base + 1] = run; run += v1;
    if (base + 2 < n) out[base + 2] = run; run += v2;
    if (base + 3 < n) out[base + 3] = run;
    if (t == 0) bsum[blockIdx.x] = sh[255];
}
__global__ void k_scan_add(int* __restrict__ out, const int* __restrict__ boff, int n) {
    int i = blockIdx.x * blockDim.x + threadIdx.x;
    if (i < n) out[i] += boff[i >> 10];
}

// ---------------- CSR fill ---------------------------------------------------
__global__ void k_csr_fill(const int* __restrict__ src, const int* __restrict__ dst,
                           const int* __restrict__ rowptr, int* __restrict__ fill,
                           int* __restrict__ esrc, int E) {
    int e = blockIdx.x * blockDim.x + threadIdx.x;
    if (e < E) {
        int d = dst[e];
        int pos = rowptr[d] + atomicAdd(&fill[d], 1);
        esrc[pos] = src[e];
    }
}

// ---------------- width-9 gather: a0 = Â x (fp32) ----------------------------
__global__ void k_gather9(const float* __restrict__ x, const float* __restrict__ dis,
                          const int* __restrict__ rowptr, const int* __restrict__ esrc,
                          float* __restrict__ out, int N) {
    int n = blockIdx.x * blockDim.x + threadIdx.x;
    if (n >= N) return;
    float dd = dis[n];
    float a[9];
#pragma unroll
    for (int f = 0; f < 9; f++) a[f] = dd * x[(size_t)n * 9 + f];
    int e0 = rowptr[n], e1 = rowptr[n + 1];
    for (int e = e0; e < e1; e++) {
        int s = esrc[e];
        float w = dis[s];
#pragma unroll
        for (int f = 0; f < 9; f++) a[f] += w * x[(size_t)s * 9 + f];
    }
#pragma unroll
    for (int f = 0; f < 9; f++) out[(size_t)n * 9 + f] = dd * a[f];
}

// ---------------- layer-1 GEMM: [N,9] @ [9,128] ------------------------------
__global__ void k_gemm1(const float* __restrict__ x, const float* __restrict__ W,
                        float* __restrict__ out, int N) {
    __shared__ float Ws[9 * 128];
    __shared__ float xs[8 * 9];
    int tid = threadIdx.x;
    for (int i = tid; i < 9 * 128; i += 256) Ws[i] = W[i];
    int r0 = blockIdx.x * 8;
    if (tid < 72) {
        int rr = tid / 9, cc = tid % 9;
        int r = r0 + rr;
        xs[tid] = (r < N) ? x[(size_t)r * 9 + cc] : 0.0f;
    }
    __syncthreads();
    int lr = tid >> 5;
    int c4 = (tid & 31) * 4;
    int r = r0 + lr;
    if (r >= N) return;
    float a0 = 0.f, a1 = 0.f, a2 = 0.f, a3 = 0.f;
#pragma unroll
    for (int k = 0; k < 9; k++) {
        float xv = xs[lr * 9 + k];
        const float* w = &Ws[k * 128 + c4];
        a0 += xv * w[0]; a1 += xv * w[1]; a2 += xv * w[2]; a3 += xv * w[3];
    }
    *(float4*)&out[(size_t)r * 128 + c4] = make_float4(a0, a1, a2, a3);
}

// ============ fused gather + tf32 mma GEMM + stats ===========================
// C[M,256] = ( Â relu(BN(Z)) ) @ W,  Z: [M,K] fp32.
// One CTA per 128-row strip; A tile built by on-the-fly CSR gather.
__device__ __forceinline__ uint32_t f2tf32(float x) {
    uint32_t u; asm("cvt.rna.tf32.f32 %0, %1;" : "=r"(u) : "f"(x)); return u;
}
__device__ __forceinline__ int swz(int k) { return ((k & 3) << 3) | (k >> 2); }
#define BIDX(k, n) ((k) * 256 + ((((n) & 127)) ^ swz(k)) + ((n) & 128))

__device__ __forceinline__ void mma_tf32(float4& c, uint32_t a0, uint32_t a1,
                                         uint32_t a2, uint32_t a3,
                                         uint32_t b0, uint32_t b1) {
    asm volatile(
        "mma.sync.aligned.m16n8k8.row.col.f32.tf32.tf32.f32 "
        "{%0,%1,%2,%3}, {%4,%5,%6,%7}, {%8,%9}, {%0,%1,%2,%3};"
        : "+f"(c.x), "+f"(c.y), "+f"(c.z), "+f"(c.w)
        : "r"(a0), "r"(a1), "r"(a2), "r"(a3), "r"(b0), "r"(b1));
}

template <int K>
__global__ void __launch_bounds__(256, 1)
k_gcn_fused(const float* __restrict__ Z, const float* __restrict__ W,
            const float* __restrict__ dis, const int* __restrict__ rowptr,
            const int* __restrict__ esrc, float* __restrict__ C, int M) {
    __shared__ uint32_t As[32 * 128];   // 16 KB
    __shared__ uint32_t Bs[32 * 256];   // 32 KB
    int tid = threadIdx.x;
    int lane = tid & 31, warp = tid >> 5;
    int g = lane >> 2, tig = lane & 3;
    int wm = warp & 3, wn = warp >> 2;
    int rowBase = blockIdx.x * 128;

    // gather mapping: warp handles 16 rows (4 groups of 4); lane = (row, col4)
    int gro = warp * 16 + (lane >> 3);   // + grp*4
    int c4 = (lane & 7) * 4;             // col-in-chunk

    float4 gacc[4];
    // ---- gather chunk k0 into gacc (BN+ReLU fused, symmetric norm) ----
    auto gather = [&](int k0) {
#pragma unroll
        for (int grp = 0; grp < 4; grp++) {
            int gr = rowBase + gro + grp * 4;
            float4 res = make_float4(0.f, 0.f, 0.f, 0.f);
            if (gr < M) {
                int cc = k0 + c4;
                float4 sc = *(const float4*)&g_scale[cc];
                float4 sh = *(const float4*)&g_shift[cc];
                int e0 = __ldg(&rowptr[gr]), e1 = __ldg(&rowptr[gr + 1]);
                float dd = __ldg(&dis[gr]);
                float4 xs_ = __ldg((const float4*)&Z[(size_t)gr * K + cc]);
                xs_.x = fmaxf(xs_.x * sc.x + sh.x, 0.f);
                xs_.y = fmaxf(xs_.y * sc.y + sh.y, 0.f);
                xs_.z = fmaxf(xs_.z * sc.z + sh.z, 0.f);
                xs_.w = fmaxf(xs_.w * sc.w + sh.w, 0.f);
                float4 acc = make_float4(0.f, 0.f, 0.f, 0.f);
                for (int e = e0; e < e1; e++) {
                    int s = __ldg(&esrc[e]);
                    float ws = __ldg(&dis[s]);
                    float4 x = __ldg((const float4*)&Z[(size_t)s * K + cc]);
                    x.x = fmaxf(x.x * sc.x + sh.x, 0.f);
                    x.y = fmaxf(x.y * sc.y + sh.y, 0.f);
                    x.z = fmaxf(x.z * sc.z + sh.z, 0.f);
                    x.w = fmaxf(x.w * sc.w + sh.w, 0.f);
                    acc.x += ws * x.x; acc.y += ws * x.y;
                    acc.z += ws * x.z; acc.w += ws * x.w;
                }
                res.x = dd * (acc.x + dd * xs_.x);
                res.y = dd * (acc.y + dd * xs_.y);
                res.z = dd * (acc.z + dd * xs_.z);
                res.w = dd * (acc.w + dd * xs_.w);
            }
            gacc[grp] = res;
        }
    };

    gather(0);

    float4 acc[2][16];
#pragma unroll
    for (int i = 0; i < 2; i++)
#pragma unroll
        for (int j = 0; j < 16; j++) acc[i][j] = make_float4(0.f, 0.f, 0.f, 0.f);

    const int nk = K >> 5;
    for (int kc = 0; kc < nk; kc++) {
        // ---- commit gathered A tile ----
#pragma unroll
        for (int grp = 0; grp < 4; grp++) {
            int r = gro + grp * 4;
            float4 v = gacc[grp];
            As[(c4 + 0) * 128 + (r ^ swz(c4 + 0))] = f2tf32(v.x);
            As[(c4 + 1) * 128 + (r ^ swz(c4 + 1))] = f2tf32(v.y);
            As[(c4 + 2) * 128 + (r ^ swz(c4 + 2))] = f2tf32(v.z);
            As[(c4 + 3) * 128 + (r ^ swz(c4 + 3))] = f2tf32(v.w);
        }
        // ---- stage B chunk: 32 x 256 ----
        int k0 = kc * 32;
#pragma unroll
        for (int l = 0; l < 8; l++) {
            int lin = l * 256 + tid;
            int k = lin >> 6;
            int n4 = (lin & 63) * 4;
            float4 w4 = *(const float4*)&W[(size_t)(k0 + k) * 256 + n4];
            Bs[BIDX(k, n4 + 0)] = f2tf32(w4.x);
            Bs[BIDX(k, n4 + 1)] = f2tf32(w4.y);
            Bs[BIDX(k, n4 + 2)] = f2tf32(w4.z);
            Bs[BIDX(k, n4 + 3)] = f2tf32(w4.w);
        }
        __syncthreads();
        // ---- prefetch-gather next chunk (overlaps MMAs) ----
        if (kc + 1 < nk) gather(k0 + 32);
        // ---- MMAs ----
#pragma unroll
        for (int s = 0; s < 4; s++) {
            int kA = s * 8 + tig;
            int kB = kA + 4;
            int xa = swz(kA), xb = swz(kB);
            uint32_t a[2][4];
#pragma unroll
            for (int mt = 0; mt < 2; mt++) {
                int m = wm * 32 + mt * 16 + g;
                a[mt][0] = As[kA * 128 + (m ^ xa)];
                a[mt][1] = As[kA * 128 + ((m + 8) ^ xa)];
                a[mt][2] = As[kB * 128 + (m ^ xb)];
                a[mt][3] = As[kB * 128 + ((m + 8) ^ xb)];
            }
#pragma unroll
            for (int nt = 0; nt < 16; nt++) {
                int n = wn * 128 + nt * 8 + g;
                uint32_t b0 = Bs[BIDX(kA, n)];
                uint32_t b1 = Bs[BIDX(kB, n)];
                mma_tf32(acc[0][nt], a[0][0], a[0][1], a[0][2], a[0][3], b0, b1);
                mma_tf32(acc[1][nt], a[1][0], a[1][1], a[1][2], a[1][3], b0, b1);
            }
        }
        __syncthreads();
    }
    // ---- store ----
#pragma unroll
    for (int mt = 0; mt < 2; mt++) {
        int r0 = rowBase + wm * 32 + mt * 16 + g;
#pragma unroll
        for (int nt = 0; nt < 16; nt++) {
            int c = wn * 128 + nt * 8 + tig * 2;
            if (r0 < M)
                *(float2*)&C[(size_t)r0 * 256 + c] = make_float2(acc[mt][nt].x, acc[mt][nt].y);
            if (r0 + 8 < M)
                *(float2*)&C[(size_t)(r0 + 8) * 256 + c] = make_float2(acc[mt][nt].z, acc[mt][nt].w);
        }
    }
    // ---- fused BN stats (exact fp32 accumulators) ----
#pragma unroll
    for (int nt = 0; nt < 16; nt++) {
        float4 u = acc[0][nt], v = acc[1][nt];
        float s0 = u.x + u.z + v.x + v.z;
        float s1 = u.y + u.w + v.y + v.w;
        float q0 = u.x * u.x + u.z * u.z + v.x * v.x + v.z * v.z;
        float q1 = u.y * u.y + u.w * u.w + v.y * v.y + v.w * v.w;
#pragma unroll
        for (int off = 4; off < 32; off <<= 1) {
            s0 += __shfl_xor_sync(0xffffffffu, s0, off);
            s1 += __shfl_xor_sync(0xffffffffu, s1, off);
            q0 += __shfl_xor_sync(0xffffffffu, q0, off);
            q1 += __shfl_xor_sync(0xffffffffu, q1, off);
        }
        if (lane < 4) {
            int c = wn * 128 + nt * 8 + lane * 2;
            atomicAdd(&g_colsum[c], s0);
            atomicAdd(&g_colsum[c + 1], s1);
            atomicAdd(&g_colsumsq[c], q0);
            atomicAdd(&g_colsumsq[c + 1], q1);
        }
    }
}

// ---------------- BN stats (layer-1 only) ------------------------------------
__global__ void k_stats(const float* __restrict__ z, int N, int H) {
    int c = threadIdx.x;
    float s = 0.f, ss = 0.f;
    for (int r = blockIdx.x; r < N; r += gridDim.x) {
        float v = z[(size_t)r * H + c];
        s += v; ss += v * v;
    }
    atomicAdd(&g_colsum[c], s);
    atomicAdd(&g_colsumsq[c], ss);
}
__global__ void k_zero_stats(int H) {
    int c = threadIdx.x;
    if (c < H) { g_colsum[c] = 0.f; g_colsumsq[c] = 0.f; }
}
__global__ void k_finalize_bn(const float* __restrict__ gam, const float* __restrict__ bet,
                              int N, int H) {
    int c = threadIdx.x;
    if (c >= H) return;
    float inv = 1.0f / (float)N;
    float mean = g_colsum[c] * inv;
    float var = fmaxf(g_colsumsq[c] * inv - mean * mean, 0.f);
    float sc = gam[c] * rsqrtf(var + BN_EPS);
    g_scale[c] = sc;
    g_shift[c] = bet[c] - mean * sc;
}

// ---------------- fp32 SGEMM (head only) with packed f32x2 -------------------
__device__ __forceinline__ unsigned long long dup_f32x2(float a) {
    unsigned long long r;
    unsigned int u = __float_as_uint(a);
    asm("mov.b64 %0, {%1, %1};" : "=l"(r) : "r"(u));
    return r;
}
__device__ __forceinline__ void fma2(unsigned long long& acc, unsigned long long a,
                                     unsigned long long b) {
    asm("fma.rn.f32x2 %0, %1, %2, %0;" : "+l"(acc) : "l"(a), "l"(b));
}
union F4U2 { float4 f; unsigned long long u[2]; };

template <bool BIAS>
__global__ void __launch_bounds__(256)
k_sgemm(const float* __restrict__ A, const float* __restrict__ W,
        float* __restrict__ C, int M, int K, int Nc,
        const float* __restrict__ bias) {
    __shared__ float As[16][132];
    __shared__ float Ws[16][128];
    int tid = threadIdx.x;
    int tx = tid & 15;
    int ty = tid >> 4;
    int rowBase = blockIdx.y * 128;
    int colBase = blockIdx.x * 128;

    unsigned long long acc2[8][4];
#pragma unroll
    for (int i = 0; i < 8; i++)
#pragma unroll
        for (int j = 0; j < 4; j++) acc2[i][j] = 0ULL;

    for (int k0 = 0; k0 < K; k0 += 16) {
#pragma unroll
        for (int l = 0; l < 2; l++) {
            int lin = tid + l * 256;
            int ar = lin >> 2;
            int ac = (lin & 3) * 4;
            int r = rowBase + ar;
            float4 v = make_float4(0.f, 0.f, 0.f, 0.f);
            if (r < M) v = *(const float4*)&A[(size_t)r * K + k0 + ac];
            As[ac + 0][ar] = v.x; As[ac + 1][ar] = v.y;
            As[ac + 2][ar] = v.z; As[ac + 3][ar] = v.w;
        }
#pragma unroll
        for (int l = 0; l < 2; l++) {
            int lin = tid + l * 256;
            int wr = lin >> 5;
            int wc = (lin & 31) * 4;
            *(float4*)&Ws[wr][wc] = *(const float4*)&W[(size_t)(k0 + wr) * Nc + colBase + wc];
        }
        __syncthreads();
#pragma unroll
        for (int k = 0; k < 16; k++) {
            F4U2 a0, a1, b0, b1;
            a0.f = *(float4*)&As[k][ty * 8];
            a1.f = *(float4*)&As[k][ty * 8 + 4];
            b0.f = *(float4*)&Ws[k][tx * 8];
            b1.f = *(float4*)&Ws[k][tx * 8 + 4];
            float av[8] = {a0.f.x, a0.f.y, a0.f.z, a0.f.w, a1.f.x, a1.f.y, a1.f.z, a1.f.w};
            unsigned long long bp[4] = {b0.u[0], b0.u[1], b1.u[0], b1.u[1]};
#pragma unroll
            for (int i = 0; i < 8; i++) {
                unsigned long long ad = dup_f32x2(av[i]);
#pragma unroll
                for (int jp = 0; jp < 4; jp++) fma2(acc2[i][jp], ad, bp[jp]);
            }
        }
        __syncthreads();
    }
#pragma unroll
    for (int i = 0; i < 8; i++) {
        int r = rowBase + ty * 8 + i;
        if (r >= M) continue;
#pragma unroll
        for (int jp = 0; jp < 4; jp += 2) {
            int c = colBase + tx * 8 + jp * 2;
            unsigned long long u0 = acc2[i][jp], u1 = acc2[i][jp + 1];
            float4 v;
            v.x = __uint_as_float((unsigned)u0);
            v.y = __uint_as_float((unsigned)(u0 >> 32));
            v.z = __uint_as_float((unsigned)u1);
            v.w = __uint_as_float((unsigned)(u1 >> 32));
            if (BIAS) { v.x += bias[c]; v.y += bias[c + 1]; v.z += bias[c + 2]; v.w += bias[c + 3]; }
            *(float4*)&C[(size_t)r * Nc + c] = v;
        }
    }
}

// ---------------- segmented pooling (BN3+ReLU fused) --------------------------
__global__ void k_pool(const float* __restrict__ z, const int* __restrict__ gptr,
                       float* __restrict__ pm) {
    int g = blockIdx.x;
    int c = threadIdx.x;
    int r0 = gptr[g], r1 = gptr[g + 1];
    float sc = g_scale[c], sh = g_shift[c];
    float s = 0.f;
    for (int r = r0; r < r1; r++) {
        float v = z[(size_t)r * 256 + c];
        s += fmaxf(v * sc + sh, 0.f);
    }
    float cnt = (float)(r1 - r0);
    pm[(size_t)g * 256 + c] = s / fmaxf(cnt, 1.0f);
}

// ---------------- host driver ------------------------------------------------
static void exclusive_scan(int* data_in, int n, int* out, int* bsum, int* boff, int* dummy) {
    int nb = (n + 1023) / 1024;
    k_scan1<<<nb, 256>>>(data_in, n, out, bsum);
    k_scan1<<<1, 256>>>(bsum, nb, boff, dummy);
    k_scan_add<<<(n + 255) / 256, 256>>>(out, boff, n);
}

extern "C" void kernel_launch(void* const* d_in, const int* in_sizes, int n_in,
                              void* d_out, int out_size) {
    const float* x = (const float*)d_in[0];
    const int* ei = (const int*)d_in[1];
    const int* batch = (const int*)d_in[2];
    int o = (in_sizes[3] == 1) ? 4 : 3;
    const float* W1 = (const float*)d_in[o + 0];
    const float* gm1 = (const float*)d_in[o + 2];
    const float* be1 = (const float*)d_in[o + 3];
    const float* W2 = (const float*)d_in[o + 4];
    const float* gm2 = (const float*)d_in[o + 6];
    const float* be2 = (const float*)d_in[o + 7];
    const float* W3 = (const float*)d_in[o + 8];
    const float* gm3 = (const float*)d_in[o + 10];
    const float* be3 = (const float*)d_in[o + 11];
    const float* Wp = (const float*)d_in[o + 12];
    const float* bp = (const float*)d_in[o + 13];

    int N = in_sizes[0] / 9;
    int E = in_sizes[1] / 2;
    int P = in_sizes[o + 13];
    int G = out_size / P;

    float *dis, *hw, *agg, *pm, *a0;
    int *rowcnt, *rowptr, *fill, *esrc, *gcnt, *gptr, *bsum, *boff, *dummy;
    cudaGetSymbolAddress((void**)&dis, g_dis);
    cudaGetSymbolAddress((void**)&hw, g_hw);
    cudaGetSymbolAddress((void**)&agg, g_agg);
    cudaGetSymbolAddress((void**)&a0, g_a0);
    cudaGetSymbolAddress((void**)&pm, g_pm);
    cudaGetSymbolAddress((void**)&rowcnt, g_rowcnt);
    cudaGetSymbolAddress((void**)&rowptr, g_rowptr);
    cudaGetSymbolAddress((void**)&fill, g_fill);
    cudaGetSymbolAddress((void**)&esrc, g_esrc);
    cudaGetSymbolAddress((void**)&gcnt, g_gcnt);
    cudaGetSymbolAddress((void**)&gptr, g_gptr);
    cudaGetSymbolAddress((void**)&bsum, g_bsum);
    cudaGetSymbolAddress((void**)&boff, g_boff);
    cudaGetSymbolAddress((void**)&dummy, g_dummy);

    const int* src = ei;
    const int* dst = ei + E;

    // ---- CSR build + norm ----
    k_zero_int<<<(N + 255) / 256, 256>>>(rowcnt, N);
    k_count<<<(E + 255) / 256, 256>>>(dst, rowcnt, E);
    k_dis<<<(N + 255) / 256, 256>>>(rowcnt, dis, N);
    exclusive_scan(rowcnt, N, rowptr, bsum, boff, dummy);
    k_set_int<<<1, 1>>>(rowptr + N, E);
    k_zero_int<<<(N + 255) / 256, 256>>>(fill, N);
    k_csr_fill<<<(E + 255) / 256, 256>>>(src, dst, rowptr, fill, esrc, E);

    // ---- graph segment ptrs (batch is sorted) ----
    k_zero_int<<<(G + 255) / 256, 256>>>(gcnt, G);
    k_count<<<(N + 255) / 256, 256>>>(batch, gcnt, N);
    exclusive_scan(gcnt, G, gptr, bsum, boff, dummy);
    k_set_int<<<1, 1>>>(gptr + G, N);

    // ---- layer 1: a0 = Âx, z1 = a0@W1 (fp32), stats, BN1 ----
    k_gather9<<<(N + 255) / 256, 256>>>(x, dis, rowptr, esrc, a0, N);
    k_gemm1<<<(N + 7) / 8, 256>>>(a0, W1, hw, N);
    k_zero_stats<<<1, 128>>>(128);
    k_stats<<<1024, 128>>>(hw, N, 128);
    k_finalize_bn<<<1, 128>>>(gm1, be1, N, 128);

    // ---- layer 2: z2 = (Â relu(BN1(z1))) @ W2, fused, stats ----
    k_zero_stats<<<1, 256>>>(256);
    k_gcn_fused<128><<<(N + 127) / 128, 256>>>(hw, W2, dis, rowptr, esrc, agg, N);
    k_finalize_bn<<<1, 256>>>(gm2, be2, N, 256);

    // ---- layer 3: z3 = (Â relu(BN2(z2))) @ W3, fused, stats ----
    k_zero_stats<<<1, 256>>>(256);
    k_gcn_fused<256><<<(N + 127) / 128, 256>>>(agg, W3, dis, rowptr, esrc, hw, N);
    k_finalize_bn<<<1, 256>>>(gm3, be3, N, 256);

    // ---- pooling over relu(BN3(z3)) ----
    k_pool<<<G, 256>>>(hw, gptr, pm);

    // ---- head (fp32, keeps output precision) ----
    {
        dim3 grid(P / 128, (G + 127) / 128);
        k_sgemm<true><<<grid, 256>>>(pm, Wp, (float*)d_out, G, 256, P, bp);
    }
}

// round 14
// speedup vs baseline: 1.7853x; 1.7853x over previous
#include <cuda_runtime.h>
#include <stdint.h>

#define NMAX 200000
#define EMAX 400000
#define GMAX 8192
#define HMAX 256
#define BN_EPS 1e-5f

// ---------------- scratch (device globals: no allocation allowed) ----------
__device__ float g_dis[NMAX];
__device__ float g_hw[(size_t)NMAX * HMAX];
__device__ float g_agg[(size_t)NMAX * HMAX];
__device__ float g_a0[(size_t)NMAX * 9];
__device__ float g_colsum[HMAX];
__device__ float g_colsumsq[HMAX];
__device__ float g_scale[HMAX];
__device__ float g_shift[HMAX];
__device__ float g_pm[(size_t)GMAX * HMAX];
__device__ int g_rowcnt[NMAX];
__device__ int g_rowptr[NMAX + 1];
__device__ int g_fill[NMAX];
__device__ int g_esrc[EMAX];
__device__ int g_gcnt[GMAX];
__device__ int g_gptr[GMAX + 1];
__device__ int g_bsum[1024];
__device__ int g_boff[1024];
__device__ int g_dummy[4];

// ---------------- small utility kernels ------------------------------------
__global__ void k_zero_int(int* p, int n) {
    int i = blockIdx.x * blockDim.x + threadIdx.x;
    if (i < n) p[i] = 0;
}
__global__ void k_set_int(int* p, int v) { *p = v; }
__global__ void k_count(const int* __restrict__ idx, int* __restrict__ cnt, int n) {
    int i = blockIdx.x * blockDim.x + threadIdx.x;
    if (i < n) atomicAdd(&cnt[idx[i]], 1);
}
__global__ void k_dis(const int* __restrict__ cnt, float* __restrict__ dis, int n) {
    int i = blockIdx.x * blockDim.x + threadIdx.x;
    if (i < n) dis[i] = rsqrtf((float)cnt[i] + 1.0f);
}

// ---------------- 2-level exclusive scan (chunk = 1024) ---------------------
__global__ void k_scan1(const int* __restrict__ in, int n, int* __restrict__ out,
                        int* __restrict__ bsum) {
    __shared__ int sh[256];
    int t = threadIdx.x;
    int base = blockIdx.x * 1024 + t * 4;
    int v0 = (base + 0 < n) ? in[base + 0] : 0;
    int v1 = (base + 1 < n) ? in[base + 1] : 0;
    int v2 = (base + 2 < n) ? in[base + 2] : 0;
    int v3 = (base + 3 < n) ? in[base + 3] : 0;
    int s = v0 + v1 + v2 + v3;
    sh[t] = s;
    __syncthreads();
    for (int off = 1; off < 256; off <<= 1) {
        int x = (t >= off) ? sh[t - off] : 0;
        __syncthreads();
        sh[t] += x;
        __syncthreads();
    }
    int run = sh[t] - s;
    if (base + 0 < n) out[base + 0] = run; run += v0;
    if (base + 1 < n) out[base + 1] = run; run += v1;
    if (base + 2 < n) out[base + 2] = run; run += v2;
    if (base + 3 < n) out[base + 3] = run;
    if (t == 0) bsum[blockIdx.x] = sh[255];
}
__global__ void k_scan_add(int* __restrict__ out, const int* __restrict__ boff, int n) {
    int i = blockIdx.x * blockDim.x + threadIdx.x;
    if (i < n) out[i] += boff[i >> 10];
}

// ---------------- CSR fill ---------------------------------------------------
__global__ void k_csr_fill(const int* __restrict__ src, const int* __restrict__ dst,
                           const int* __restrict__ rowptr, int* __restrict__ fill,
                           int* __restrict__ esrc, int E) {
    int e = blockIdx.x * blockDim.x + threadIdx.x;
    if (e < E) {
        int d = dst[e];
        int pos = rowptr[d] + atomicAdd(&fill[d], 1);
        esrc[pos] = src[e];
    }
}

// ---------------- width-9 gather: a0 = Â x ----------------------------------
__global__ void k_gather9(const float* __restrict__ x, const float* __restrict__ dis,
                          const int* __restrict__ rowptr, const int* __restrict__ esrc,
                          float* __restrict__ out, int N) {
    int n = blockIdx.x * blockDim.x + threadIdx.x;
    if (n >= N) return;
    float dd = dis[n];
    float a[9];
#pragma unroll
    for (int f = 0; f < 9; f++) a[f] = dd * x[(size_t)n * 9 + f];
    int e0 = rowptr[n], e1 = rowptr[n + 1];
    for (int e = e0; e < e1; e++) {
        int s = esrc[e];
        float w = dis[s];
#pragma unroll
        for (int f = 0; f < 9; f++) a[f] += w * x[(size_t)s * 9 + f];
    }
#pragma unroll
    for (int f = 0; f < 9; f++) out[(size_t)n * 9 + f] = dd * a[f];
}

// ---------------- layer-1 GEMM: [N,9] @ [9,128] ------------------------------
__global__ void k_gemm1(const float* __restrict__ x, const float* __restrict__ W,
                        float* __restrict__ out, int N) {
    __shared__ float Ws[9 * 128];
    __shared__ float xs[8 * 9];
    int tid = threadIdx.x;
    for (int i = tid; i < 9 * 128; i += 256) Ws[i] = W[i];
    int r0 = blockIdx.x * 8;
    if (tid < 72) {
        int rr = tid / 9, cc = tid % 9;
        int r = r0 + rr;
        xs[tid] = (r < N) ? x[(size_t)r * 9 + cc] : 0.0f;
    }
    __syncthreads();
    int lr = tid >> 5;
    int c4 = (tid & 31) * 4;
    int r = r0 + lr;
    if (r >= N) return;
    float a0 = 0.f, a1 = 0.f, a2 = 0.f, a3 = 0.f;
#pragma unroll
    for (int k = 0; k < 9; k++) {
        float xv = xs[lr * 9 + k];
        const float* w = &Ws[k * 128 + c4];
        a0 += xv * w[0]; a1 += xv * w[1]; a2 += xv * w[2]; a3 += xv * w[3];
    }
    *(float4*)&out[(size_t)r * 128 + c4] = make_float4(a0, a1, a2, a3);
}

// ================= tf32 mma.sync GEMM (128x256 tile) + fused stats ==========
__device__ __forceinline__ uint32_t f2tf32(float x) {
    uint32_t u; asm("cvt.rna.tf32.f32 %0, %1;" : "=r"(u) : "f"(x)); return u;
}
__device__ __forceinline__ int swz(int k) { return ((k & 3) << 3) | (k >> 2); }
#define BIDX(k, n) ((k) * 256 + ((((n) & 127)) ^ swz(k)) + ((n) & 128))

__device__ __forceinline__ void mma_tf32(float4& c, uint32_t a0, uint32_t a1,
                                         uint32_t a2, uint32_t a3,
                                         uint32_t b0, uint32_t b1) {
    asm volatile(
        "mma.sync.aligned.m16n8k8.row.col.f32.tf32.tf32.f32 "
        "{%0,%1,%2,%3}, {%4,%5,%6,%7}, {%8,%9}, {%0,%1,%2,%3};"
        : "+f"(c.x), "+f"(c.y), "+f"(c.z), "+f"(c.w)
        : "r"(a0), "r"(a1), "r"(a2), "r"(a3), "r"(b0), "r"(b1));
}

// C[M,256] = A[M,K] @ W[K,256]; one CTA per 128-row strip (A read ONCE).
// Register double-buffering on both A and B; fused per-column stats.
template <int K>
__global__ void __launch_bounds__(256, 1)
k_gemm_mma(const float* __restrict__ A, const float* __restrict__ W,
           float* __restrict__ C, int M) {
    __shared__ uint32_t As[32 * 128];   // 16 KB
    __shared__ uint32_t Bs[32 * 256];   // 32 KB
    int tid = threadIdx.x;
    int lane = tid & 31, warp = tid >> 5;
    int g = lane >> 2, tig = lane & 3;
    int wm = warp & 3, wn = warp >> 2;
    int rowBase = blockIdx.x * 128;

    // A: 4 float4/thread (128x32 words); B: 8 float4/thread (32x256 words)
    int ar[4], akq[4], bk[8], bn4[8];
#pragma unroll
    for (int l = 0; l < 4; l++) {
        int lin = l * 256 + tid;
        ar[l] = lin >> 3;
        akq[l] = (lin & 7) * 4;
    }
#pragma unroll
    for (int l = 0; l < 8; l++) {
        int lin = l * 256 + tid;
        bk[l] = lin >> 6;
        bn4[l] = (lin & 63) * 4;
    }

    float4 av[4], bv[8];
#pragma unroll
    for (int l = 0; l < 4; l++) {
        int gr = rowBase + ar[l];
        av[l] = make_float4(0.f, 0.f, 0.f, 0.f);
        if (gr < M) av[l] = *(const float4*)&A[(size_t)gr * K + akq[l]];
    }
#pragma unroll
    for (int l = 0; l < 8; l++)
        bv[l] = *(const float4*)&W[(size_t)bk[l] * 256 + bn4[l]];

    float4 acc[2][16];
#pragma unroll
    for (int i = 0; i < 2; i++)
#pragma unroll
        for (int j = 0; j < 16; j++) acc[i][j] = make_float4(0.f, 0.f, 0.f, 0.f);

    const int nk = K >> 5;
    for (int kc = 0; kc < nk; kc++) {
#pragma unroll
        for (int l = 0; l < 4; l++) {
            int r = ar[l], kq = akq[l];
            float4 v = av[l];
            As[(kq + 0) * 128 + (r ^ swz(kq + 0))] = f2tf32(v.x);
            As[(kq + 1) * 128 + (r ^ swz(kq + 1))] = f2tf32(v.y);
            As[(kq + 2) * 128 + (r ^ swz(kq + 2))] = f2tf32(v.z);
            As[(kq + 3) * 128 + (r ^ swz(kq + 3))] = f2tf32(v.w);
        }
#pragma unroll
        for (int l = 0; l < 8; l++) {
            int k = bk[l], n4 = bn4[l];
            float4 v = bv[l];
            Bs[BIDX(k, n4 + 0)] = f2tf32(v.x);
            Bs[BIDX(k, n4 + 1)] = f2tf32(v.y);
            Bs[BIDX(k, n4 + 2)] = f2tf32(v.z);
            Bs[BIDX(k, n4 + 3)] = f2tf32(v.w);
        }
        __syncthreads();
        if (kc + 1 < nk) {
            int k0 = (kc + 1) * 32;
#pragma unroll
            for (int l = 0; l < 4; l++) {
                int gr = rowBase + ar[l];
                av[l] = make_float4(0.f, 0.f, 0.f, 0.f);
                if (gr < M) av[l] = *(const float4*)&A[(size_t)gr * K + k0 + akq[l]];
            }
#pragma unroll
            for (int l = 0; l < 8; l++)
                bv[l] = *(const float4*)&W[(size_t)(k0 + bk[l]) * 256 + bn4[l]];
        }
#pragma unroll
        for (int s = 0; s < 4; s++) {
            int kA = s * 8 + tig;
            int kB = kA + 4;
            int xa = swz(kA), xb = swz(kB);
            uint32_t a[2][4];
#pragma unroll
            for (int mt = 0; mt < 2; mt++) {
                int m = wm * 32 + mt * 16 + g;
                a[mt][0] = As[kA * 128 + (m ^ xa)];
                a[mt][1] = As[kA * 128 + ((m + 8) ^ xa)];
                a[mt][2] = As[kB * 128 + (m ^ xb)];
                a[mt][3] = As[kB * 128 + ((m + 8) ^ xb)];
            }
#pragma unroll
            for (int nt = 0; nt < 16; nt++) {
                int n = wn * 128 + nt * 8 + g;
                uint32_t b0 = Bs[BIDX(kA, n)];
                uint32_t b1 = Bs[BIDX(kB, n)];
                mma_tf32(acc[0][nt], a[0][0], a[0][1], a[0][2], a[0][3], b0, b1);
                mma_tf32(acc[1][nt], a[1][0], a[1][1], a[1][2], a[1][3], b0, b1);
            }
        }
        __syncthreads();
    }
    // ---- store ----
#pragma unroll
    for (int mt = 0; mt < 2; mt++) {
        int r0 = rowBase + wm * 32 + mt * 16 + g;
#pragma unroll
        for (int nt = 0; nt < 16; nt++) {
            int c = wn * 128 + nt * 8 + tig * 2;
            if (r0 < M)
                *(float2*)&C[(size_t)r0 * 256 + c] = make_float2(acc[mt][nt].x, acc[mt][nt].y);
            if (r0 + 8 < M)
                *(float2*)&C[(size_t)(r0 + 8) * 256 + c] = make_float2(acc[mt][nt].z, acc[mt][nt].w);
        }
    }
    // ---- fused BN stats (exact fp32 accumulators) ----
#pragma unroll
    for (int nt = 0; nt < 16; nt++) {
        float4 u = acc[0][nt], v = acc[1][nt];
        float s0 = u.x + u.z + v.x + v.z;
        float s1 = u.y + u.w + v.y + v.w;
        float q0 = u.x * u.x + u.z * u.z + v.x * v.x + v.z * v.z;
        float q1 = u.y * u.y + u.w * u.w + v.y * v.y + v.w * v.w;
#pragma unroll
        for (int off = 4; off < 32; off <<= 1) {
            s0 += __shfl_xor_sync(0xffffffffu, s0, off);
            s1 += __shfl_xor_sync(0xffffffffu, s1, off);
            q0 += __shfl_xor_sync(0xffffffffu, q0, off);
            q1 += __shfl_xor_sync(0xffffffffu, q1, off);
        }
        if (lane < 4) {
            int c = wn * 128 + nt * 8 + lane * 2;
            atomicAdd(&g_colsum[c], s0);
            atomicAdd(&g_colsum[c + 1], s1);
            atomicAdd(&g_colsumsq[c], q0);
            atomicAdd(&g_colsumsq[c + 1], q1);
        }
    }
}

// ---------------- CSR gather: warp per (node, 128-col slice), pipelined ------
template <int H, bool BN>
__global__ void k_gather(const float* __restrict__ hw, const float* __restrict__ dis,
                         const int* __restrict__ rowptr, const int* __restrict__ esrc,
                         float* __restrict__ agg, int N) {
    constexpr int S = H / 128;
    int w = (blockIdx.x * blockDim.x + threadIdx.x) >> 5;
    int lane = threadIdx.x & 31;
    int n = (S == 1) ? w : (w >> 1);
    int sl = (S == 1) ? 0 : (w & 1);
    if (n >= N) return;
    int c = sl * 128 + lane * 4;

    float4 sc, sh;
    if (BN) {
        sc = *(const float4*)&g_scale[c];
        sh = *(const float4*)&g_shift[c];
    }
    int e0 = __ldg(&rowptr[n]), e1 = __ldg(&rowptr[n + 1]);
    float dd = __ldg(&dis[n]);

    float4 acc = make_float4(0.f, 0.f, 0.f, 0.f);
    int s_nxt = 0; float w_nxt = 0.f;
    if (e0 < e1) { s_nxt = __ldg(&esrc[e0]); w_nxt = __ldg(&dis[s_nxt]); }
    for (int e = e0; e < e1; e++) {
        int s = s_nxt; float ws = w_nxt;
        if (e + 1 < e1) { s_nxt = __ldg(&esrc[e + 1]); w_nxt = __ldg(&dis[s_nxt]); }
        float4 x = __ldg((const float4*)&hw[(size_t)s * H + c]);
        if (BN) {
            x.x = fmaxf(x.x * sc.x + sh.x, 0.f);
            x.y = fmaxf(x.y * sc.y + sh.y, 0.f);
            x.z = fmaxf(x.z * sc.z + sh.z, 0.f);
            x.w = fmaxf(x.w * sc.w + sh.w, 0.f);
        }
        acc.x += ws * x.x; acc.y += ws * x.y;
        acc.z += ws * x.z; acc.w += ws * x.w;
    }
    float4 x = __ldg((const float4*)&hw[(size_t)n * H + c]);
    if (BN) {
        x.x = fmaxf(x.x * sc.x + sh.x, 0.f);
        x.y = fmaxf(x.y * sc.y + sh.y, 0.f);
        x.z = fmaxf(x.z * sc.z + sh.z, 0.f);
        x.w = fmaxf(x.w * sc.w + sh.w, 0.f);
    }
    float4 r;
    r.x = dd * (acc.x + dd * x.x);
    r.y = dd * (acc.y + dd * x.y);
    r.z = dd * (acc.z + dd * x.z);
    r.w = dd * (acc.w + dd * x.w);
    *(float4*)&agg[(size_t)n * H + c] = r;
}

// ---------------- BN stats (layer-1 only) ------------------------------------
__global__ void k_stats(const float* __restrict__ z, int N, int H) {
    int c = threadIdx.x;
    float s = 0.f, ss = 0.f;
    for (int r = blockIdx.x; r < N; r += gridDim.x) {
        float v = z[(size_t)r * H + c];
        s += v; ss += v * v;
    }
    atomicAdd(&g_colsum[c], s);
    atomicAdd(&g_colsumsq[c], ss);
}
__global__ void k_zero_stats(int H) {
    int c = threadIdx.x;
    if (c < H) { g_colsum[c] = 0.f; g_colsumsq[c] = 0.f; }
}
__global__ void k_finalize_bn(const float* __restrict__ gam, const float* __restrict__ bet,
                              int N, int H) {
    int c = threadIdx.x;
    if (c >= H) return;
    float inv = 1.0f / (float)N;
    float mean = g_colsum[c] * inv;
    float var = fmaxf(g_colsumsq[c] * inv - mean * mean, 0.f);
    float sc = gam[c] * rsqrtf(var + BN_EPS);
    g_scale[c] = sc;
    g_shift[c] = bet[c] - mean * sc;
}

// ---------------- fp32 SGEMM (head only) with packed f32x2 -------------------
__device__ __forceinline__ unsigned long long dup_f32x2(float a) {
    unsigned long long r;
    unsigned int u = __float_as_uint(a);
    asm("mov.b64 %0, {%1, %1};" : "=l"(r) : "r"(u));
    return r;
}
__device__ __forceinline__ void fma2(unsigned long long& acc, unsigned long long a,
                                     unsigned long long b) {
    asm("fma.rn.f32x2 %0, %1, %2, %0;" : "+l"(acc) : "l"(a), "l"(b));
}
union F4U2 { float4 f; unsigned long long u[2]; };

template <bool BIAS>
__global__ void __launch_bounds__(256)
k_sgemm(const float* __restrict__ A, const float* __restrict__ W,
        float* __restrict__ C, int M, int K, int Nc,
        const float* __restrict__ bias) {
    __shared__ float As[16][132];
    __shared__ float Ws[16][128];
    int tid = threadIdx.x;
    int tx = tid & 15;
    int ty = tid >> 4;
    int rowBase = blockIdx.y * 128;
    int colBase = blockIdx.x * 128;

    unsigned long long acc2[8][4];
#pragma unroll
    for (int i = 0; i < 8; i++)
#pragma unroll
        for (int j = 0; j < 4; j++) acc2[i][j] = 0ULL;

    for (int k0 = 0; k0 < K; k0 += 16) {
#pragma unroll
        for (int l = 0; l < 2; l++) {
            int lin = tid + l * 256;
            int ar = lin >> 2;
            int ac = (lin & 3) * 4;
            int r = rowBase + ar;
            float4 v = make_float4(0.f, 0.f, 0.f, 0.f);
            if (r < M) v = *(const float4*)&A[(size_t)r * K + k0 + ac];
            As[ac + 0][ar] = v.x; As[ac + 1][ar] = v.y;
            As[ac + 2][ar] = v.z; As[ac + 3][ar] = v.w;
        }
#pragma unroll
        for (int l = 0; l < 2; l++) {
            int lin = tid + l * 256;
            int wr = lin >> 5;
            int wc = (lin & 31) * 4;
            *(float4*)&Ws[wr][wc] = *(const float4*)&W[(size_t)(k0 + wr) * Nc + colBase + wc];
        }
        __syncthreads();
#pragma unroll
        for (int k = 0; k < 16; k++) {
            F4U2 a0, a1, b0, b1;
            a0.f = *(float4*)&As[k][ty * 8];
            a1.f = *(float4*)&As[k][ty * 8 + 4];
            b0.f = *(float4*)&Ws[k][tx * 8];
            b1.f = *(float4*)&Ws[k][tx * 8 + 4];
            float av[8] = {a0.f.x, a0.f.y, a0.f.z, a0.f.w, a1.f.x, a1.f.y, a1.f.z, a1.f.w};
            unsigned long long bp[4] = {b0.u[0], b0.u[1], b1.u[0], b1.u[1]};
#pragma unroll
            for (int i = 0; i < 8; i++) {
                unsigned long long ad = dup_f32x2(av[i]);
#pragma unroll
                for (int jp = 0; jp < 4; jp++) fma2(acc2[i][jp], ad, bp[jp]);
            }
        }
        __syncthreads();
    }
#pragma unroll
    for (int i = 0; i < 8; i++) {
        int r = rowBase + ty * 8 + i;
        if (r >= M) continue;
#pragma unroll
        for (int jp = 0; jp < 4; jp += 2) {
            int c = colBase + tx * 8 + jp * 2;
            unsigned long long u0 = acc2[i][jp], u1 = acc2[i][jp + 1];
            float4 v;
            v.x = __uint_as_float((unsigned)u0);
            v.y = __uint_as_float((unsigned)(u0 >> 32));
            v.z = __uint_as_float((unsigned)u1);
            v.w = __uint_as_float((unsigned)(u1 >> 32));
            if (BIAS) { v.x += bias[c]; v.y += bias[c + 1]; v.z += bias[c + 2]; v.w += bias[c + 3]; }
            *(float4*)&C[(size_t)r * Nc + c] = v;
        }
    }
}

// ---------------- segmented pooling (BN3+ReLU fused) --------------------------
__global__ void k_pool(const float* __restrict__ z, const int* __restrict__ gptr,
                       float* __restrict__ pm) {
    int g = blockIdx.x;
    int c = threadIdx.x;
    int r0 = gptr[g], r1 = gptr[g + 1];
    float sc = g_scale[c], sh = g_shift[c];
    float s = 0.f;
    for (int r = r0; r < r1; r++) {
        float v = z[(size_t)r * 256 + c];
        s += fmaxf(v * sc + sh, 0.f);
    }
    float cnt = (float)(r1 - r0);
    pm[(size_t)g * 256 + c] = s / fmaxf(cnt, 1.0f);
}

// ---------------- host driver ------------------------------------------------
static void exclusive_scan(int* data_in, int n, int* out, int* bsum, int* boff, int* dummy) {
    int nb = (n + 1023) / 1024;
    k_scan1<<<nb, 256>>>(data_in, n, out, bsum);
    k_scan1<<<1, 256>>>(bsum, nb, boff, dummy);
    k_scan_add<<<(n + 255) / 256, 256>>>(out, boff, n);
}

extern "C" void kernel_launch(void* const* d_in, const int* in_sizes, int n_in,
                              void* d_out, int out_size) {
    const float* x = (const float*)d_in[0];
    const int* ei = (const int*)d_in[1];
    const int* batch = (const int*)d_in[2];
    int o = (in_sizes[3] == 1) ? 4 : 3;
    const float* W1 = (const float*)d_in[o + 0];
    const float* gm1 = (const float*)d_in[o + 2];
    const float* be1 = (const float*)d_in[o + 3];
    const float* W2 = (const float*)d_in[o + 4];
    const float* gm2 = (const float*)d_in[o + 6];
    const float* be2 = (const float*)d_in[o + 7];
    const float* W3 = (const float*)d_in[o + 8];
    const float* gm3 = (const float*)d_in[o + 10];
    const float* be3 = (const float*)d_in[o + 11];
    const float* Wp = (const float*)d_in[o + 12];
    const float* bp = (const float*)d_in[o + 13];

    int N = in_sizes[0] / 9;
    int E = in_sizes[1] / 2;
    int P = in_sizes[o + 13];
    int G = out_size / P;

    float *dis, *hw, *agg, *pm, *a0;
    int *rowcnt, *rowptr, *fill, *esrc, *gcnt, *gptr, *bsum, *boff, *dummy;
    cudaGetSymbolAddress((void**)&dis, g_dis);
    cudaGetSymbolAddress((void**)&hw, g_hw);
    cudaGetSymbolAddress((void**)&agg, g_agg);
    cudaGetSymbolAddress((void**)&a0, g_a0);
    cudaGetSymbolAddress((void**)&pm, g_pm);
    cudaGetSymbolAddress((void**)&rowcnt, g_rowcnt);
    cudaGetSymbolAddress((void**)&rowptr, g_rowptr);
    cudaGetSymbolAddress((void**)&fill, g_fill);
    cudaGetSymbolAddress((void**)&esrc, g_esrc);
    cudaGetSymbolAddress((void**)&gcnt, g_gcnt);
    cudaGetSymbolAddress((void**)&gptr, g_gptr);
    cudaGetSymbolAddress((void**)&bsum, g_bsum);
    cudaGetSymbolAddress((void**)&boff, g_boff);
    cudaGetSymbolAddress((void**)&dummy, g_dummy);

    const int* src = ei;
    const int* dst = ei + E;

    // ---- CSR build + norm ----
    k_zero_int<<<(N + 255) / 256, 256>>>(rowcnt, N);
    k_count<<<(E + 255) / 256, 256>>>(dst, rowcnt, E);
    k_dis<<<(N + 255) / 256, 256>>>(rowcnt, dis, N);
    exclusive_scan(rowcnt, N, rowptr, bsum, boff, dummy);
    k_set_int<<<1, 1>>>(rowptr + N, E);
    k_zero_int<<<(N + 255) / 256, 256>>>(fill, N);
    k_csr_fill<<<(E + 255) / 256, 256>>>(src, dst, rowptr, fill, esrc, E);

    // ---- graph segment ptrs (batch is sorted) ----
    k_zero_int<<<(G + 255) / 256, 256>>>(gcnt, G);
    k_count<<<(N + 255) / 256, 256>>>(batch, gcnt, N);
    exclusive_scan(gcnt, G, gptr, bsum, boff, dummy);
    k_set_int<<<1, 1>>>(gptr + G, N);

    // ---- layer 1: a0 = Âx, z1 = a0@W1 (fp32), stats, BN1 ----
    k_gather9<<<(N + 255) / 256, 256>>>(x, dis, rowptr, esrc, a0, N);
    k_gemm1<<<(N + 7) / 8, 256>>>(a0, W1, hw, N);
    k_zero_stats<<<1, 128>>>(128);
    k_stats<<<1024, 128>>>(hw, N, 128);
    k_finalize_bn<<<1, 128>>>(gm1, be1, N, 128);

    // ---- layer 2: a1 = Â relu(BN1(z1)) (width 128), z2 = a1@W2 (+stats) ----
    k_gather<128, true><<<(N + 7) / 8, 256>>>(hw, dis, rowptr, esrc, agg, N);
    k_zero_stats<<<1, 256>>>(256);
    k_gemm_mma<128><<<(N + 127) / 128, 256>>>(agg, W2, hw, N);
    k_finalize_bn<<<1, 256>>>(gm2, be2, N, 256);

    // ---- layer 3: a2 = Â relu(BN2(z2)) (width 256, 2 warps/node), z3 ----
    k_gather<256, true><<<(2 * N + 7) / 8, 256>>>(hw, dis, rowptr, esrc, agg, N);
    k_zero_stats<<<1, 256>>>(256);
    k_gemm_mma<256><<<(N + 127) / 128, 256>>>(agg, W3, hw, N);
    k_finalize_bn<<<1, 256>>>(gm3, be3, N, 256);

    // ---- pooling over relu(BN3(z3)) ----
    k_pool<<<G, 256>>>(hw, gptr, pm);

    // ---- head (fp32, keeps output precision) ----
    {
        dim3 grid(P / 128, (G + 127) / 128);
        k_sgemm<true><<<grid, 256>>>(pm, Wp, (float*)d_out, G, 256, P, bp);
    }
}

// round 15
// speedup vs baseline: 2.0032x; 1.1220x over previous
#include <cuda_runtime.h>
#include <stdint.h>

#define NMAX 200000
#define EMAX 400000
#define GMAX 8192
#define HMAX 256
#define BN_EPS 1e-5f

// ---------------- scratch (device globals: no allocation allowed) ----------
__device__ float g_dis[NMAX];
__device__ float g_hw[(size_t)NMAX * HMAX];
__device__ float g_agg[(size_t)NMAX * HMAX];
__device__ float g_a0[(size_t)NMAX * 9];
__device__ float g_colsum[3 * 256];     // per-layer stats
__device__ float g_colsumsq[3 * 256];
__device__ float g_pm[(size_t)GMAX * HMAX];
__device__ int g_rowcnt[NMAX];
__device__ int g_rowptr[NMAX + 1];
__device__ int g_fill[NMAX];
__device__ int g_esrc[EMAX];
__device__ int g_gcnt[GMAX];
__device__ int g_gptr[GMAX + 1];
__device__ int g_bsum[1024];
__device__ int g_boff[1024];
__device__ int g_dummy[4];

// ---------------- fused setup: zero all counters + stats --------------------
__global__ void k_setup(int* rowcnt, int* fill, int* gcnt, int N, int G) {
    int i = blockIdx.x * blockDim.x + threadIdx.x;
    if (i < N) { rowcnt[i] = 0; fill[i] = 0; }
    if (i < G) gcnt[i] = 0;
    if (i < 3 * 256) { g_colsum[i] = 0.f; g_colsumsq[i] = 0.f; }
}

__global__ void k_set_int(int* p, int v) { *p = v; }
__global__ void k_count(const int* __restrict__ idx, int* __restrict__ cnt, int n) {
    int i = blockIdx.x * blockDim.x + threadIdx.x;
    if (i < n) atomicAdd(&cnt[idx[i]], 1);
}
__global__ void k_dis(const int* __restrict__ cnt, float* __restrict__ dis, int n) {
    int i = blockIdx.x * blockDim.x + threadIdx.x;
    if (i < n) dis[i] = rsqrtf((float)cnt[i] + 1.0f);
}

// ---------------- 2-level exclusive scan (chunk = 1024) ---------------------
__global__ void k_scan1(const int* __restrict__ in, int n, int* __restrict__ out,
                        int* __restrict__ bsum) {
    __shared__ int sh[256];
    int t = threadIdx.x;
    int base = blockIdx.x * 1024 + t * 4;
    int v0 = (base + 0 < n) ? in[base + 0] : 0;
    int v1 = (base + 1 < n) ? in[base + 1] : 0;
    int v2 = (base + 2 < n) ? in[base + 2] : 0;
    int v3 = (base + 3 < n) ? in[base + 3] : 0;
    int s = v0 + v1 + v2 + v3;
    sh[t] = s;
    __syncthreads();
    for (int off = 1; off < 256; off <<= 1) {
        int x = (t >= off) ? sh[t - off] : 0;
        __syncthreads();
        sh[t] += x;
        __syncthreads();
    }
    int run = sh[t] - s;
    if (base + 0 < n) out[base + 0] = run; run += v0;
    if (base + 1 < n) out[base + 1] = run; run += v1;
    if (base + 2 < n) out[base + 2] = run; run += v2;
    if (base + 3 < n) out[base + 3] = run;
    if (t == 0) bsum[blockIdx.x] = sh[255];
}
__global__ void k_scan_add(int* __restrict__ out, const int* __restrict__ boff, int n) {
    int i = blockIdx.x * blockDim.x + threadIdx.x;
    if (i < n) out[i] += boff[i >> 10];
}

// ---------------- CSR fill ---------------------------------------------------
__global__ void k_csr_fill(const int* __restrict__ src, const int* __restrict__ dst,
                           const int* __restrict__ rowptr, int* __restrict__ fill,
                           int* __restrict__ esrc, int E) {
    int e = blockIdx.x * blockDim.x + threadIdx.x;
    if (e < E) {
        int d = dst[e];
        int pos = rowptr[d] + atomicAdd(&fill[d], 1);
        esrc[pos] = src[e];
    }
}

// ---------------- width-9 gather: a0 = Â x ----------------------------------
__global__ void k_gather9(const float* __restrict__ x, const float* __restrict__ dis,
                          const int* __restrict__ rowptr, const int* __restrict__ esrc,
                          float* __restrict__ out, int N) {
    int n = blockIdx.x * blockDim.x + threadIdx.x;
    if (n >= N) return;
    float dd = dis[n];
    float a[9];
#pragma unroll
    for (int f = 0; f < 9; f++) a[f] = dd * x[(size_t)n * 9 + f];
    int e0 = rowptr[n], e1 = rowptr[n + 1];
    for (int e = e0; e < e1; e++) {
        int s = esrc[e];
        float w = dis[s];
#pragma unroll
        for (int f = 0; f < 9; f++) a[f] += w * x[(size_t)s * 9 + f];
    }
#pragma unroll
    for (int f = 0; f < 9; f++) out[(size_t)n * 9 + f] = dd * a[f];
}

// ---------------- layer-1 GEMM: [N,9]@[9,128], 32 rows/block, fused stats ----
__global__ void __launch_bounds__(256)
k_gemm1(const float* __restrict__ x, const float* __restrict__ W,
        float* __restrict__ out, int N) {
    __shared__ float Ws[9 * 128];
    __shared__ float xs[32 * 9];
    __shared__ float red[2][8][128];
    int tid = threadIdx.x;
    for (int i = tid; i < 9 * 128; i += 256) Ws[i] = W[i];
    int r0 = blockIdx.x * 32;
    for (int i = tid; i < 32 * 9; i += 256) {
        int rr = i / 9, cc = i % 9;
        int r = r0 + rr;
        xs[i] = (r < N) ? x[(size_t)r * 9 + cc] : 0.0f;
    }
    __syncthreads();
    int lr = tid >> 5;            // 0..7 -> 4 rows each
    int c4 = (tid & 31) * 4;      // 0..124
    float s[4] = {0.f, 0.f, 0.f, 0.f}, q[4] = {0.f, 0.f, 0.f, 0.f};
#pragma unroll
    for (int i = 0; i < 4; i++) {
        int rr = lr * 4 + i;
        int r = r0 + rr;
        float a0 = 0.f, a1 = 0.f, a2 = 0.f, a3 = 0.f;
#pragma unroll
        for (int k = 0; k < 9; k++) {
            float xv = xs[rr * 9 + k];
            const float* w = &Ws[k * 128 + c4];
            a0 += xv * w[0]; a1 += xv * w[1]; a2 += xv * w[2]; a3 += xv * w[3];
        }
        if (r < N) {
            *(float4*)&out[(size_t)r * 128 + c4] = make_float4(a0, a1, a2, a3);
            s[0] += a0; s[1] += a1; s[2] += a2; s[3] += a3;
            q[0] += a0 * a0; q[1] += a1 * a1; q[2] += a2 * a2; q[3] += a3 * a3;
        }
    }
#pragma unroll
    for (int j = 0; j < 4; j++) { red[0][lr][c4 + j] = s[j]; red[1][lr][c4 + j] = q[j]; }
    __syncthreads();
    if (lr == 0) {
#pragma unroll
        for (int j = 0; j < 4; j++) {
            float ts = 0.f, tq = 0.f;
#pragma unroll
            for (int l = 0; l < 8; l++) { ts += red[0][l][c4 + j]; tq += red[1][l][c4 + j]; }
            atomicAdd(&g_colsum[c4 + j], ts);       // layer 0
            atomicAdd(&g_colsumsq[c4 + j], tq);
        }
    }
}

// ================= tf32 mma.sync GEMM (128x128 tile) ========================
__device__ __forceinline__ uint32_t f2tf32(float x) {
    uint32_t u; asm("cvt.rna.tf32.f32 %0, %1;" : "=r"(u) : "f"(x)); return u;
}
__device__ __forceinline__ int swz(int k) { return ((k & 3) << 3) | (k >> 2); }

__device__ __forceinline__ void mma_tf32(float4& c, uint32_t a0, uint32_t a1,
                                         uint32_t a2, uint32_t a3,
                                         uint32_t b0, uint32_t b1) {
    asm volatile(
        "mma.sync.aligned.m16n8k8.row.col.f32.tf32.tf32.f32 "
        "{%0,%1,%2,%3}, {%4,%5,%6,%7}, {%8,%9}, {%0,%1,%2,%3};"
        : "+f"(c.x), "+f"(c.y), "+f"(c.z), "+f"(c.w)
        : "r"(a0), "r"(a1), "r"(a2), "r"(a3), "r"(b0), "r"(b1));
}

// C[M,Nc] = A[M,K] @ W[K,Nc] (+bias); block tile 128x128, K-chunk 32.
// STATS: per-column sum/sumsq into layer buffer so=256*layer.
template <bool STATS, bool BIAS>
__global__ void __launch_bounds__(256, 1)
k_gemm_mma(const float* __restrict__ A, const float* __restrict__ W,
           float* __restrict__ C, int M, int K, int Nc, int so,
           const float* __restrict__ bias) {
    __shared__ uint32_t As[32 * 128];
    __shared__ uint32_t Bs[32 * 128];
    int tid = threadIdx.x;
    int lane = tid & 31, warp = tid >> 5;
    int g = lane >> 2, tig = lane & 3;
    int wm = warp & 3, wn = warp >> 2;
    int rowBase = blockIdx.y * 128;
    int colBase = blockIdx.x * 128;

    int ar[4], akq[4], bk[4], bn4[4];
#pragma unroll
    for (int l = 0; l < 4; l++) {
        int lin = l * 256 + tid;
        ar[l] = lin >> 3;
        akq[l] = (lin & 7) * 4;
        bk[l] = lin >> 5;
        bn4[l] = (lin & 31) * 4;
    }

    float4 av[4], bv[4];
#pragma unroll
    for (int l = 0; l < 4; l++) {
        int gr = rowBase + ar[l];
        av[l] = make_float4(0.f, 0.f, 0.f, 0.f);
        if (gr < M) av[l] = *(const float4*)&A[(size_t)gr * K + akq[l]];
        bv[l] = *(const float4*)&W[(size_t)bk[l] * Nc + colBase + bn4[l]];
    }

    float4 acc[2][8];
#pragma unroll
    for (int i = 0; i < 2; i++)
#pragma unroll
        for (int j = 0; j < 8; j++) acc[i][j] = make_float4(0.f, 0.f, 0.f, 0.f);

    int nk = K >> 5;
    for (int kc = 0; kc < nk; kc++) {
#pragma unroll
        for (int l = 0; l < 4; l++) {
            int r = ar[l], kq = akq[l];
            As[(kq + 0) * 128 + (r ^ swz(kq + 0))] = f2tf32(av[l].x);
            As[(kq + 1) * 128 + (r ^ swz(kq + 1))] = f2tf32(av[l].y);
            As[(kq + 2) * 128 + (r ^ swz(kq + 2))] = f2tf32(av[l].z);
            As[(kq + 3) * 128 + (r ^ swz(kq + 3))] = f2tf32(av[l].w);
            int k = bk[l], n4 = bn4[l];
            int xk = swz(k);
            Bs[k * 128 + ((n4 + 0) ^ xk)] = f2tf32(bv[l].x);
            Bs[k * 128 + ((n4 + 1) ^ xk)] = f2tf32(bv[l].y);
            Bs[k * 128 + ((n4 + 2) ^ xk)] = f2tf32(bv[l].z);
            Bs[k * 128 + ((n4 + 3) ^ xk)] = f2tf32(bv[l].w);
        }
        __syncthreads();
        if (kc + 1 < nk) {
            int k0 = (kc + 1) * 32;
#pragma unroll
            for (int l = 0; l < 4; l++) {
                int gr = rowBase + ar[l];
                av[l] = make_float4(0.f, 0.f, 0.f, 0.f);
                if (gr < M) av[l] = *(const float4*)&A[(size_t)gr * K + k0 + akq[l]];
                bv[l] = *(const float4*)&W[(size_t)(k0 + bk[l]) * Nc + colBase + bn4[l]];
            }
        }
#pragma unroll
        for (int s = 0; s < 4; s++) {
            int kA = s * 8 + tig;
            int kB = kA + 4;
            int xa = swz(kA), xb = swz(kB);
            uint32_t a[2][4];
#pragma unroll
            for (int mt = 0; mt < 2; mt++) {
                int m = wm * 32 + mt * 16 + g;
                a[mt][0] = As[kA * 128 + (m ^ xa)];
                a[mt][1] = As[kA * 128 + ((m + 8) ^ xa)];
                a[mt][2] = As[kB * 128 + (m ^ xb)];
                a[mt][3] = As[kB * 128 + ((m + 8) ^ xb)];
            }
#pragma unroll
            for (int nt = 0; nt < 8; nt++) {
                int n = wn * 64 + nt * 8 + g;
                uint32_t b0 = Bs[kA * 128 + (n ^ xa)];
                uint32_t b1 = Bs[kB * 128 + (n ^ xb)];
                mma_tf32(acc[0][nt], a[0][0], a[0][1], a[0][2], a[0][3], b0, b1);
                mma_tf32(acc[1][nt], a[1][0], a[1][1], a[1][2], a[1][3], b0, b1);
            }
        }
        __syncthreads();
    }
#pragma unroll
    for (int mt = 0; mt < 2; mt++) {
        int r0 = rowBase + wm * 32 + mt * 16 + g;
#pragma unroll
        for (int nt = 0; nt < 8; nt++) {
            int c = colBase + wn * 64 + nt * 8 + tig * 2;
            float2 v0 = make_float2(acc[mt][nt].x, acc[mt][nt].y);
            float2 v1 = make_float2(acc[mt][nt].z, acc[mt][nt].w);
            if (BIAS) {
                v0.x += bias[c]; v0.y += bias[c + 1];
                v1.x += bias[c]; v1.y += bias[c + 1];
            }
            if (r0 < M) *(float2*)&C[(size_t)r0 * Nc + c] = v0;
            if (r0 + 8 < M) *(float2*)&C[(size_t)(r0 + 8) * Nc + c] = v1;
        }
    }
    if (STATS) {
#pragma unroll
        for (int nt = 0; nt < 8; nt++) {
            float4 u = acc[0][nt], v = acc[1][nt];
            float s0 = u.x + u.z + v.x + v.z;
            float s1 = u.y + u.w + v.y + v.w;
            float q0 = u.x * u.x + u.z * u.z + v.x * v.x + v.z * v.z;
            float q1 = u.y * u.y + u.w * u.w + v.y * v.y + v.w * v.w;
#pragma unroll
            for (int off = 4; off < 32; off <<= 1) {
                s0 += __shfl_xor_sync(0xffffffffu, s0, off);
                s1 += __shfl_xor_sync(0xffffffffu, s1, off);
                q0 += __shfl_xor_sync(0xffffffffu, q0, off);
                q1 += __shfl_xor_sync(0xffffffffu, q1, off);
            }
            if (lane < 4) {
                int c = colBase + wn * 64 + nt * 8 + lane * 2;
                atomicAdd(&g_colsum[so + c], s0);
                atomicAdd(&g_colsum[so + c + 1], s1);
                atomicAdd(&g_colsumsq[so + c], q0);
                atomicAdd(&g_colsumsq[so + c + 1], q1);
            }
        }
    }
}

// ---------------- CSR gather with in-block BN compute -------------------------
// out[d,slice] = dis[d] * ( sum_e dis[s]*relu(BN(hw[s])) + dis[d]*relu(BN(hw[d])) )
template <int H>
__global__ void __launch_bounds__(256)
k_gather(const float* __restrict__ hw, const float* __restrict__ dis,
         const int* __restrict__ rowptr, const int* __restrict__ esrc,
         float* __restrict__ agg, int N, int so,
         const float* __restrict__ gam, const float* __restrict__ bet) {
    constexpr int S = H / 128;
    __shared__ __align__(16) float s_sc[H];
    __shared__ __align__(16) float s_sh[H];
    int tid = threadIdx.x;
    if (tid < H) {
        float inv = 1.0f / (float)N;
        float mean = g_colsum[so + tid] * inv;
        float var = fmaxf(g_colsumsq[so + tid] * inv - mean * mean, 0.f);
        float sc = gam[tid] * rsqrtf(var + BN_EPS);
        s_sc[tid] = sc;
        s_sh[tid] = bet[tid] - mean * sc;
    }
    __syncthreads();

    int w = (blockIdx.x * blockDim.x + tid) >> 5;
    int lane = tid & 31;
    int n = (S == 1) ? w : (w >> 1);
    int sl = (S == 1) ? 0 : (w & 1);
    if (n >= N) return;
    int c = sl * 128 + lane * 4;

    float4 sc = *(const float4*)&s_sc[c];
    float4 sh = *(const float4*)&s_sh[c];
    int e0 = __ldg(&rowptr[n]), e1 = __ldg(&rowptr[n + 1]);
    float dd = __ldg(&dis[n]);

    float4 acc = make_float4(0.f, 0.f, 0.f, 0.f);
    int s_nxt = 0; float w_nxt = 0.f;
    if (e0 < e1) { s_nxt = __ldg(&esrc[e0]); w_nxt = __ldg(&dis[s_nxt]); }
    for (int e = e0; e < e1; e++) {
        int s = s_nxt; float ws = w_nxt;
        if (e + 1 < e1) { s_nxt = __ldg(&esrc[e + 1]); w_nxt = __ldg(&dis[s_nxt]); }
        float4 x = __ldg((const float4*)&hw[(size_t)s * H + c]);
        x.x = fmaxf(x.x * sc.x + sh.x, 0.f);
        x.y = fmaxf(x.y * sc.y + sh.y, 0.f);
        x.z = fmaxf(x.z * sc.z + sh.z, 0.f);
        x.w = fmaxf(x.w * sc.w + sh.w, 0.f);
        acc.x += ws * x.x; acc.y += ws * x.y;
        acc.z += ws * x.z; acc.w += ws * x.w;
    }
    float4 x = __ldg((const float4*)&hw[(size_t)n * H + c]);
    x.x = fmaxf(x.x * sc.x + sh.x, 0.f);
    x.y = fmaxf(x.y * sc.y + sh.y, 0.f);
    x.z = fmaxf(x.z * sc.z + sh.z, 0.f);
    x.w = fmaxf(x.w * sc.w + sh.w, 0.f);
    float4 r;
    r.x = dd * (acc.x + dd * x.x);
    r.y = dd * (acc.y + dd * x.y);
    r.z = dd * (acc.z + dd * x.z);
    r.w = dd * (acc.w + dd * x.w);
    *(float4*)&agg[(size_t)n * H + c] = r;
}

// ---------------- segmented pooling (BN3+ReLU computed in-thread) -------------
__global__ void k_pool(const float* __restrict__ z, const int* __restrict__ gptr,
                       float* __restrict__ pm, int N, int so,
                       const float* __restrict__ gam, const float* __restrict__ bet) {
    int g = blockIdx.x;
    int c = threadIdx.x;
    float inv = 1.0f / (float)N;
    float mean = g_colsum[so + c] * inv;
    float var = fmaxf(g_colsumsq[so + c] * inv - mean * mean, 0.f);
    float sc = gam[c] * rsqrtf(var + BN_EPS);
    float sh = bet[c] - mean * sc;
    int r0 = gptr[g], r1 = gptr[g + 1];
    float s = 0.f;
    for (int r = r0; r < r1; r++) {
        float v = z[(size_t)r * 256 + c];
        s += fmaxf(v * sc + sh, 0.f);
    }
    float cnt = (float)(r1 - r0);
    pm[(size_t)g * 256 + c] = s / fmaxf(cnt, 1.0f);
}

// ---------------- host driver ------------------------------------------------
static void exclusive_scan(int* data_in, int n, int* out, int* bsum, int* boff, int* dummy) {
    int nb = (n + 1023) / 1024;
    k_scan1<<<nb, 256>>>(data_in, n, out, bsum);
    k_scan1<<<1, 256>>>(bsum, nb, boff, dummy);
    k_scan_add<<<(n + 255) / 256, 256>>>(out, boff, n);
}

extern "C" void kernel_launch(void* const* d_in, const int* in_sizes, int n_in,
                              void* d_out, int out_size) {
    const float* x = (const float*)d_in[0];
    const int* ei = (const int*)d_in[1];
    const int* batch = (const int*)d_in[2];
    int o = (in_sizes[3] == 1) ? 4 : 3;
    const float* W1 = (const float*)d_in[o + 0];
    const float* gm1 = (const float*)d_in[o + 2];
    const float* be1 = (const float*)d_in[o + 3];
    const float* W2 = (const float*)d_in[o + 4];
    const float* gm2 = (const float*)d_in[o + 6];
    const float* be2 = (const float*)d_in[o + 7];
    const float* W3 = (const float*)d_in[o + 8];
    const float* gm3 = (const float*)d_in[o + 10];
    const float* be3 = (const float*)d_in[o + 11];
    const float* Wp = (const float*)d_in[o + 12];
    const float* bp = (const float*)d_in[o + 13];

    int N = in_sizes[0] / 9;
    int E = in_sizes[1] / 2;
    int P = in_sizes[o + 13];
    int G = out_size / P;

    float *dis, *hw, *agg, *pm, *a0;
    int *rowcnt, *rowptr, *fill, *esrc, *gcnt, *gptr, *bsum, *boff, *dummy;
    cudaGetSymbolAddress((void**)&dis, g_dis);
    cudaGetSymbolAddress((void**)&hw, g_hw);
    cudaGetSymbolAddress((void**)&agg, g_agg);
    cudaGetSymbolAddress((void**)&a0, g_a0);
    cudaGetSymbolAddress((void**)&pm, g_pm);
    cudaGetSymbolAddress((void**)&rowcnt, g_rowcnt);
    cudaGetSymbolAddress((void**)&rowptr, g_rowptr);
    cudaGetSymbolAddress((void**)&fill, g_fill);
    cudaGetSymbolAddress((void**)&esrc, g_esrc);
    cudaGetSymbolAddress((void**)&gcnt, g_gcnt);
    cudaGetSymbolAddress((void**)&gptr, g_gptr);
    cudaGetSymbolAddress((void**)&bsum, g_bsum);
    cudaGetSymbolAddress((void**)&boff, g_boff);
    cudaGetSymbolAddress((void**)&dummy, g_dummy);

    const int* src = ei;
    const int* dst = ei + E;

    // ---- fused setup + CSR build + norm ----
    k_setup<<<(N + 255) / 256, 256>>>(rowcnt, fill, gcnt, N, G);
    k_count<<<(E + 255) / 256, 256>>>(dst, rowcnt, E);
    k_dis<<<(N + 255) / 256, 256>>>(rowcnt, dis, N);
    exclusive_scan(rowcnt, N, rowptr, bsum, boff, dummy);
    k_set_int<<<1, 1>>>(rowptr + N, E);
    k_csr_fill<<<(E + 255) / 256, 256>>>(src, dst, rowptr, fill, esrc, E);

    // ---- graph segment ptrs (batch is sorted) ----
    k_count<<<(N + 255) / 256, 256>>>(batch, gcnt, N);
    exclusive_scan(gcnt, G, gptr, bsum, boff, dummy);
    k_set_int<<<1, 1>>>(gptr + G, N);

    // ---- layer 1: a0 = Âx, z1 = a0@W1 (fused stats -> layer 0) ----
    k_gather9<<<(N + 255) / 256, 256>>>(x, dis, rowptr, esrc, a0, N);
    k_gemm1<<<(N + 31) / 32, 256>>>(a0, W1, hw, N);

    // ---- layer 2: a1 = Â relu(BN0(z1)), z2 = a1@W2 (stats -> layer 1) ----
    k_gather<128><<<(N + 7) / 8, 256>>>(hw, dis, rowptr, esrc, agg, N, 0, gm1, be1);
    {
        dim3 grid(2, (N + 127) / 128);
        k_gemm_mma<true, false><<<grid, 256>>>(agg, W2, hw, N, 128, 256, 256, nullptr);
    }

    // ---- layer 3: a2 = Â relu(BN1(z2)), z3 = a2@W3 (stats -> layer 2) ----
    k_gather<256><<<(2 * N + 7) / 8, 256>>>(hw, dis, rowptr, esrc, agg, N, 256, gm2, be2);
    {
        dim3 grid(2, (N + 127) / 128);
        k_gemm_mma<true, false><<<grid, 256>>>(agg, W3, hw, N, 256, 256, 512, nullptr);
    }

    // ---- pooling over relu(BN2(z3)) ----
    k_pool<<<G, 256>>>(hw, gptr, pm, N, 512, gm3, be3);

    // ---- head: d_out = pm @ Wp + bp (tf32 mma) ----
    {
        dim3 grid(P / 128, (G + 127) / 128);
        k_gemm_mma<false, true><<<grid, 256>>>(pm, Wp, (float*)d_out, G, 256, P, 0, bp);
    }
}

// round 16
// speedup vs baseline: 2.0085x; 1.0027x over previous
#include <cuda_runtime.h>
#include <stdint.h>

#define NMAX 200000
#define EMAX 400000
#define GMAX 8192
#define HMAX 256
#define BN_EPS 1e-5f

// ---------------- scratch (device globals: no allocation allowed) ----------
__device__ float g_dis[NMAX];
__device__ float g_hw[(size_t)NMAX * HMAX];
__device__ float g_agg[(size_t)NMAX * HMAX];
__device__ float g_a0[(size_t)NMAX * 9];
__device__ float g_colsum[3 * 256];
__device__ float g_colsumsq[3 * 256];
__device__ float g_pm[(size_t)GMAX * HMAX];
__device__ int g_rowcnt[NMAX];
__device__ int g_rowptr[NMAX + 1];
__device__ int g_fill[NMAX];
__device__ int g_esrc[EMAX];
__device__ int g_gcnt[GMAX];
__device__ int g_gptr[GMAX + 1];
__device__ int g_bsum[1024];
__device__ int g_boff[1024];

// ---------------- fused setup: zero all counters + stats --------------------
__global__ void k_setup(int* rowcnt, int* fill, int* gcnt, int N, int G) {
    int i = blockIdx.x * blockDim.x + threadIdx.x;
    if (i < N) { rowcnt[i] = 0; fill[i] = 0; }
    if (i < G) gcnt[i] = 0;
    if (i < 3 * 256) { g_colsum[i] = 0.f; g_colsumsq[i] = 0.f; }
}

// ---------------- fused counting: degrees + graph sizes ----------------------
__global__ void k_count2(const int* __restrict__ dst, const int* __restrict__ batch,
                         int* __restrict__ rowcnt, int* __restrict__ gcnt, int E, int N) {
    int i = blockIdx.x * blockDim.x + threadIdx.x;
    if (i < E) atomicAdd(&rowcnt[dst[i]], 1);
    if (i < N) atomicAdd(&gcnt[batch[i]], 1);
}

// ---------------- scan core (1024 elems/block) -------------------------------
__device__ __forceinline__ void scan_block(const int* __restrict__ in, int n,
                                           int* __restrict__ out, int* __restrict__ bsum,
                                           int blk) {
    __shared__ int sh[256];
    int t = threadIdx.x;
    int base = blk * 1024 + t * 4;
    int v0 = (base + 0 < n) ? in[base + 0] : 0;
    int v1 = (base + 1 < n) ? in[base + 1] : 0;
    int v2 = (base + 2 < n) ? in[base + 2] : 0;
    int v3 = (base + 3 < n) ? in[base + 3] : 0;
    int s = v0 + v1 + v2 + v3;
    sh[t] = s;
    __syncthreads();
    for (int off = 1; off < 256; off <<= 1) {
        int x = (t >= off) ? sh[t - off] : 0;
        __syncthreads();
        sh[t] += x;
        __syncthreads();
    }
    int run = sh[t] - s;
    if (base + 0 < n) out[base + 0] = run; run += v0;
    if (base + 1 < n) out[base + 1] = run; run += v1;
    if (base + 2 < n) out[base + 2] = run; run += v2;
    if (base + 3 < n) out[base + 3] = run;
    if (t == 0) bsum[blk] = sh[255];
}

// level-1 dual scan: blocks [0,nbN) scan rowcnt->rowptr, [nbN, nbN+nbG) gcnt->gptr
__global__ void k_scan1_dual(const int* __restrict__ rowcnt, int N,
                             const int* __restrict__ gcnt, int G, int nbN) {
    int b = blockIdx.x;
    if (b < nbN) scan_block(rowcnt, N, g_rowptr, g_bsum, b);
    else scan_block(gcnt, G, g_gptr, g_bsum + 512, b - nbN);
}

// level-2: block 0 scans bsum[0..nbN), block 1 scans bsum[512..512+nbG)
__global__ void k_scan2(int nbN, int nbG) {
    __shared__ int dummy;
    int* d = &dummy;
    if (blockIdx.x == 0) scan_block(g_bsum, nbN, g_boff, d, 0);
    else scan_block(g_bsum + 512, nbG, g_boff + 512, d, 0);
}

// add block offsets; compute dis; write sentinel tails
__global__ void k_scan_add_dual(int* __restrict__ rowptr, int* __restrict__ gptr,
                                const int* __restrict__ rowcnt,
                                float* __restrict__ dis, int N, int G, int E) {
    int i = blockIdx.x * blockDim.x + threadIdx.x;
    if (i < N) {
        rowptr[i] += g_boff[i >> 10];
        dis[i] = rsqrtf((float)rowcnt[i] + 1.0f);
    }
    if (i < G) gptr[i] += g_boff[512 + (i >> 10)];
    if (i == 0) { rowptr[N] = E; gptr[G] = N; }
}

// ---------------- CSR fill ---------------------------------------------------
__global__ void k_csr_fill(const int* __restrict__ src, const int* __restrict__ dst,
                           const int* __restrict__ rowptr, int* __restrict__ fill,
                           int* __restrict__ esrc, int E) {
    int e = blockIdx.x * blockDim.x + threadIdx.x;
    if (e < E) {
        int d = dst[e];
        int pos = rowptr[d] + atomicAdd(&fill[d], 1);
        esrc[pos] = src[e];
    }
}

// ---------------- width-9 gather: a0 = Â x ----------------------------------
__global__ void k_gather9(const float* __restrict__ x, const float* __restrict__ dis,
                          const int* __restrict__ rowptr, const int* __restrict__ esrc,
                          float* __restrict__ out, int N) {
    int n = blockIdx.x * blockDim.x + threadIdx.x;
    if (n >= N) return;
    float dd = dis[n];
    float a[9];
#pragma unroll
    for (int f = 0; f < 9; f++) a[f] = dd * x[(size_t)n * 9 + f];
    int e0 = rowptr[n], e1 = rowptr[n + 1];
    for (int e = e0; e < e1; e++) {
        int s = esrc[e];
        float w = dis[s];
#pragma unroll
        for (int f = 0; f < 9; f++) a[f] += w * x[(size_t)s * 9 + f];
    }
#pragma unroll
    for (int f = 0; f < 9; f++) out[(size_t)n * 9 + f] = dd * a[f];
}

// ---------------- layer-1 GEMM: [N,9]@[9,128], 32 rows/block, fused stats ----
__global__ void __launch_bounds__(256)
k_gemm1(const float* __restrict__ x, const float* __restrict__ W,
        float* __restrict__ out, int N) {
    __shared__ float Ws[9 * 128];
    __shared__ float xs[32 * 9];
    __shared__ float red[2][8][128];
    int tid = threadIdx.x;
    for (int i = tid; i < 9 * 128; i += 256) Ws[i] = W[i];
    int r0 = blockIdx.x * 32;
    for (int i = tid; i < 32 * 9; i += 256) {
        int rr = i / 9, cc = i % 9;
        int r = r0 + rr;
        xs[i] = (r < N) ? x[(size_t)r * 9 + cc] : 0.0f;
    }
    __syncthreads();
    int lr = tid >> 5;
    int c4 = (tid & 31) * 4;
    float s[4] = {0.f, 0.f, 0.f, 0.f}, q[4] = {0.f, 0.f, 0.f, 0.f};
#pragma unroll
    for (int i = 0; i < 4; i++) {
        int rr = lr * 4 + i;
        int r = r0 + rr;
        float a0 = 0.f, a1 = 0.f, a2 = 0.f, a3 = 0.f;
#pragma unroll
        for (int k = 0; k < 9; k++) {
            float xv = xs[rr * 9 + k];
            const float* w = &Ws[k * 128 + c4];
            a0 += xv * w[0]; a1 += xv * w[1]; a2 += xv * w[2]; a3 += xv * w[3];
        }
        if (r < N) {
            *(float4*)&out[(size_t)r * 128 + c4] = make_float4(a0, a1, a2, a3);
            s[0] += a0; s[1] += a1; s[2] += a2; s[3] += a3;
            q[0] += a0 * a0; q[1] += a1 * a1; q[2] += a2 * a2; q[3] += a3 * a3;
        }
    }
#pragma unroll
    for (int j = 0; j < 4; j++) { red[0][lr][c4 + j] = s[j]; red[1][lr][c4 + j] = q[j]; }
    __syncthreads();
    if (lr == 0) {
#pragma unroll
        for (int j = 0; j < 4; j++) {
            float ts = 0.f, tq = 0.f;
#pragma unroll
            for (int l = 0; l < 8; l++) { ts += red[0][l][c4 + j]; tq += red[1][l][c4 + j]; }
            atomicAdd(&g_colsum[c4 + j], ts);
            atomicAdd(&g_colsumsq[c4 + j], tq);
        }
    }
}

// ================= tf32 mma.sync GEMM (128x128 tile) ========================
__device__ __forceinline__ uint32_t f2tf32(float x) {
    uint32_t u; asm("cvt.rna.tf32.f32 %0, %1;" : "=r"(u) : "f"(x)); return u;
}
__device__ __forceinline__ int swz(int k) { return ((k & 3) << 3) | (k >> 2); }

__device__ __forceinline__ void mma_tf32(float4& c, uint32_t a0, uint32_t a1,
                                         uint32_t a2, uint32_t a3,
                                         uint32_t b0, uint32_t b1) {
    asm volatile(
        "mma.sync.aligned.m16n8k8.row.col.f32.tf32.tf32.f32 "
        "{%0,%1,%2,%3}, {%4,%5,%6,%7}, {%8,%9}, {%0,%1,%2,%3};"
        : "+f"(c.x), "+f"(c.y), "+f"(c.z), "+f"(c.w)
        : "r"(a0), "r"(a1), "r"(a2), "r"(a3), "r"(b0), "r"(b1));
}

template <bool STATS, bool BIAS>
__global__ void __launch_bounds__(256, 1)
k_gemm_mma(const float* __restrict__ A, const float* __restrict__ W,
           float* __restrict__ C, int M, int K, int Nc, int so,
           const float* __restrict__ bias) {
    __shared__ uint32_t As[32 * 128];
    __shared__ uint32_t Bs[32 * 128];
    int tid = threadIdx.x;
    int lane = tid & 31, warp = tid >> 5;
    int g = lane >> 2, tig = lane & 3;
    int wm = warp & 3, wn = warp >> 2;
    int rowBase = blockIdx.y * 128;
    int colBase = blockIdx.x * 128;

    int ar[4], akq[4], bk[4], bn4[4];
#pragma unroll
    for (int l = 0; l < 4; l++) {
        int lin = l * 256 + tid;
        ar[l] = lin >> 3;
        akq[l] = (lin & 7) * 4;
        bk[l] = lin >> 5;
        bn4[l] = (lin & 31) * 4;
    }

    float4 av[4], bv[4];
#pragma unroll
    for (int l = 0; l < 4; l++) {
        int gr = rowBase + ar[l];
        av[l] = make_float4(0.f, 0.f, 0.f, 0.f);
        if (gr < M) av[l] = *(const float4*)&A[(size_t)gr * K + akq[l]];
        bv[l] = *(const float4*)&W[(size_t)bk[l] * Nc + colBase + bn4[l]];
    }

    float4 acc[2][8];
#pragma unroll
    for (int i = 0; i < 2; i++)
#pragma unroll
        for (int j = 0; j < 8; j++) acc[i][j] = make_float4(0.f, 0.f, 0.f, 0.f);

    int nk = K >> 5;
    for (int kc = 0; kc < nk; kc++) {
#pragma unroll
        for (int l = 0; l < 4; l++) {
            int r = ar[l], kq = akq[l];
            As[(kq + 0) * 128 + (r ^ swz(kq + 0))] = f2tf32(av[l].x);
            As[(kq + 1) * 128 + (r ^ swz(kq + 1))] = f2tf32(av[l].y);
            As[(kq + 2) * 128 + (r ^ swz(kq + 2))] = f2tf32(av[l].z);
            As[(kq + 3) * 128 + (r ^ swz(kq + 3))] = f2tf32(av[l].w);
            int k = bk[l], n4 = bn4[l];
            int xk = swz(k);
            Bs[k * 128 + ((n4 + 0) ^ xk)] = f2tf32(bv[l].x);
            Bs[k * 128 + ((n4 + 1) ^ xk)] = f2tf32(bv[l].y);
            Bs[k * 128 + ((n4 + 2) ^ xk)] = f2tf32(bv[l].z);
            Bs[k * 128 + ((n4 + 3) ^ xk)] = f2tf32(bv[l].w);
        }
        __syncthreads();
        if (kc + 1 < nk) {
            int k0 = (kc + 1) * 32;
#pragma unroll
            for (int l = 0; l < 4; l++) {
                int gr = rowBase + ar[l];
                av[l] = make_float4(0.f, 0.f, 0.f, 0.f);
                if (gr < M) av[l] = *(const float4*)&A[(size_t)gr * K + k0 + akq[l]];
                bv[l] = *(const float4*)&W[(size_t)(k0 + bk[l]) * Nc + colBase + bn4[l]];
            }
        }
#pragma unroll
        for (int s = 0; s < 4; s++) {
            int kA = s * 8 + tig;
            int kB = kA + 4;
            int xa = swz(kA), xb = swz(kB);
            uint32_t a[2][4];
#pragma unroll
            for (int mt = 0; mt < 2; mt++) {
                int m = wm * 32 + mt * 16 + g;
                a[mt][0] = As[kA * 128 + (m ^ xa)];
                a[mt][1] = As[kA * 128 + ((m + 8) ^ xa)];
                a[mt][2] = As[kB * 128 + (m ^ xb)];
                a[mt][3] = As[kB * 128 + ((m + 8) ^ xb)];
            }
#pragma unroll
            for (int nt = 0; nt < 8; nt++) {
                int n = wn * 64 + nt * 8 + g;
                uint32_t b0 = Bs[kA * 128 + (n ^ xa)];
                uint32_t b1 = Bs[kB * 128 + (n ^ xb)];
                mma_tf32(acc[0][nt], a[0][0], a[0][1], a[0][2], a[0][3], b0, b1);
                mma_tf32(acc[1][nt], a[1][0], a[1][1], a[1][2], a[1][3], b0, b1);
            }
        }
        __syncthreads();
    }
#pragma unroll
    for (int mt = 0; mt < 2; mt++) {
        int r0 = rowBase + wm * 32 + mt * 16 + g;
#pragma unroll
        for (int nt = 0; nt < 8; nt++) {
            int c = colBase + wn * 64 + nt * 8 + tig * 2;
            float2 v0 = make_float2(acc[mt][nt].x, acc[mt][nt].y);
            float2 v1 = make_float2(acc[mt][nt].z, acc[mt][nt].w);
            if (BIAS) {
                v0.x += bias[c]; v0.y += bias[c + 1];
                v1.x += bias[c]; v1.y += bias[c + 1];
            }
            if (r0 < M) *(float2*)&C[(size_t)r0 * Nc + c] = v0;
            if (r0 + 8 < M) *(float2*)&C[(size_t)(r0 + 8) * Nc + c] = v1;
        }
    }
    if (STATS) {
#pragma unroll
        for (int nt = 0; nt < 8; nt++) {
            float4 u = acc[0][nt], v = acc[1][nt];
            float s0 = u.x + u.z + v.x + v.z;
            float s1 = u.y + u.w + v.y + v.w;
            float q0 = u.x * u.x + u.z * u.z + v.x * v.x + v.z * v.z;
            float q1 = u.y * u.y + u.w * u.w + v.y * v.y + v.w * v.w;
#pragma unroll
            for (int off = 4; off < 32; off <<= 1) {
                s0 += __shfl_xor_sync(0xffffffffu, s0, off);
                s1 += __shfl_xor_sync(0xffffffffu, s1, off);
                q0 += __shfl_xor_sync(0xffffffffu, q0, off);
                q1 += __shfl_xor_sync(0xffffffffu, q1, off);
            }
            if (lane < 4) {
                int c = colBase + wn * 64 + nt * 8 + lane * 2;
                atomicAdd(&g_colsum[so + c], s0);
                atomicAdd(&g_colsum[so + c + 1], s1);
                atomicAdd(&g_colsumsq[so + c], q0);
                atomicAdd(&g_colsumsq[so + c + 1], q1);
            }
        }
    }
}

// ---------------- CSR gather with in-block BN compute -------------------------
template <int H>
__global__ void __launch_bounds__(256)
k_gather(const float* __restrict__ hw, const float* __restrict__ dis,
         const int* __restrict__ rowptr, const int* __restrict__ esrc,
         float* __restrict__ agg, int N, int so,
         const float* __restrict__ gam, const float* __restrict__ bet) {
    constexpr int S = H / 128;
    __shared__ __align__(16) float s_sc[H];
    __shared__ __align__(16) float s_sh[H];
    int tid = threadIdx.x;
    if (tid < H) {
        float inv = 1.0f / (float)N;
        float mean = g_colsum[so + tid] * inv;
        float var = fmaxf(g_colsumsq[so + tid] * inv - mean * mean, 0.f);
        float sc = gam[tid] * rsqrtf(var + BN_EPS);
        s_sc[tid] = sc;
        s_sh[tid] = bet[tid] - mean * sc;
    }
    __syncthreads();

    int w = (blockIdx.x * blockDim.x + tid) >> 5;
    int lane = tid & 31;
    int n = (S == 1) ? w : (w >> 1);
    int sl = (S == 1) ? 0 : (w & 1);
    if (n >= N) return;
    int c = sl * 128 + lane * 4;

    float4 sc = *(const float4*)&s_sc[c];
    float4 sh = *(const float4*)&s_sh[c];
    int e0 = __ldg(&rowptr[n]), e1 = __ldg(&rowptr[n + 1]);
    float dd = __ldg(&dis[n]);

    float4 acc = make_float4(0.f, 0.f, 0.f, 0.f);
    int s_nxt = 0; float w_nxt = 0.f;
    if (e0 < e1) { s_nxt = __ldg(&esrc[e0]); w_nxt = __ldg(&dis[s_nxt]); }
    for (int e = e0; e < e1; e++) {
        int s = s_nxt; float ws = w_nxt;
        if (e + 1 < e1) { s_nxt = __ldg(&esrc[e + 1]); w_nxt = __ldg(&dis[s_nxt]); }
        float4 x = __ldg((const float4*)&hw[(size_t)s * H + c]);
        x.x = fmaxf(x.x * sc.x + sh.x, 0.f);
        x.y = fmaxf(x.y * sc.y + sh.y, 0.f);
        x.z = fmaxf(x.z * sc.z + sh.z, 0.f);
        x.w = fmaxf(x.w * sc.w + sh.w, 0.f);
        acc.x += ws * x.x; acc.y += ws * x.y;
        acc.z += ws * x.z; acc.w += ws * x.w;
    }
    float4 x = __ldg((const float4*)&hw[(size_t)n * H + c]);
    x.x = fmaxf(x.x * sc.x + sh.x, 0.f);
    x.y = fmaxf(x.y * sc.y + sh.y, 0.f);
    x.z = fmaxf(x.z * sc.z + sh.z, 0.f);
    x.w = fmaxf(x.w * sc.w + sh.w, 0.f);
    float4 r;
    r.x = dd * (acc.x + dd * x.x);
    r.y = dd * (acc.y + dd * x.y);
    r.z = dd * (acc.z + dd * x.z);
    r.w = dd * (acc.w + dd * x.w);
    *(float4*)&agg[(size_t)n * H + c] = r;
}

// ---------------- segmented pooling (BN3+ReLU computed in-thread) -------------
__global__ void k_pool(const float* __restrict__ z, const int* __restrict__ gptr,
                       float* __restrict__ pm, int N, int so,
                       const float* __restrict__ gam, const float* __restrict__ bet) {
    int g = blockIdx.x;
    int c = threadIdx.x;
    float inv = 1.0f / (float)N;
    float mean = g_colsum[so + c] * inv;
    float var = fmaxf(g_colsumsq[so + c] * inv - mean * mean, 0.f);
    float sc = gam[c] * rsqrtf(var + BN_EPS);
    float sh = bet[c] - mean * sc;
    int r0 = gptr[g], r1 = gptr[g + 1];
    float s0 = 0.f, s1 = 0.f;
    int r = r0;
    for (; r + 1 < r1; r += 2) {
        float v0 = z[(size_t)r * 256 + c];
        float v1 = z[(size_t)(r + 1) * 256 + c];
        s0 += fmaxf(v0 * sc + sh, 0.f);
        s1 += fmaxf(v1 * sc + sh, 0.f);
    }
    if (r < r1) s0 += fmaxf(z[(size_t)r * 256 + c] * sc + sh, 0.f);
    float cnt = (float)(r1 - r0);
    pm[(size_t)g * 256 + c] = (s0 + s1) / fmaxf(cnt, 1.0f);
}

// ---------------- host driver ------------------------------------------------
extern "C" void kernel_launch(void* const* d_in, const int* in_sizes, int n_in,
                              void* d_out, int out_size) {
    const float* x = (const float*)d_in[0];
    const int* ei = (const int*)d_in[1];
    const int* batch = (const int*)d_in[2];
    int o = (in_sizes[3] == 1) ? 4 : 3;
    const float* W1 = (const float*)d_in[o + 0];
    const float* gm1 = (const float*)d_in[o + 2];
    const float* be1 = (const float*)d_in[o + 3];
    const float* W2 = (const float*)d_in[o + 4];
    const float* gm2 = (const float*)d_in[o + 6];
    const float* be2 = (const float*)d_in[o + 7];
    const float* W3 = (const float*)d_in[o + 8];
    const float* gm3 = (const float*)d_in[o + 10];
    const float* be3 = (const float*)d_in[o + 11];
    const float* Wp = (const float*)d_in[o + 12];
    const float* bp = (const float*)d_in[o + 13];

    int N = in_sizes[0] / 9;
    int E = in_sizes[1] / 2;
    int P = in_sizes[o + 13];
    int G = out_size / P;

    float *dis, *hw, *agg, *pm, *a0;
    int *rowcnt, *rowptr, *fill, *esrc, *gcnt, *gptr;
    cudaGetSymbolAddress((void**)&dis, g_dis);
    cudaGetSymbolAddress((void**)&hw, g_hw);
    cudaGetSymbolAddress((void**)&agg, g_agg);
    cudaGetSymbolAddress((void**)&a0, g_a0);
    cudaGetSymbolAddress((void**)&pm, g_pm);
    cudaGetSymbolAddress((void**)&rowcnt, g_rowcnt);
    cudaGetSymbolAddress((void**)&rowptr, g_rowptr);
    cudaGetSymbolAddress((void**)&fill, g_fill);
    cudaGetSymbolAddress((void**)&esrc, g_esrc);
    cudaGetSymbolAddress((void**)&gcnt, g_gcnt);
    cudaGetSymbolAddress((void**)&gptr, g_gptr);

    const int* src = ei;
    const int* dst = ei + E;

    int nbN = (N + 1023) / 1024;
    int nbG = (G + 1023) / 1024;

    // ---- prologue: 6 launches total ----
    k_setup<<<(N + 255) / 256, 256>>>(rowcnt, fill, gcnt, N, G);
    k_count2<<<(E + 255) / 256, 256>>>(dst, batch, rowcnt, gcnt, E, N);
    k_scan1_dual<<<nbN + nbG, 256>>>(rowcnt, N, gcnt, G, nbN);
    k_scan2<<<2, 256>>>(nbN, nbG);
    k_scan_add_dual<<<(N + 255) / 256, 256>>>(rowptr, gptr, rowcnt, dis, N, G, E);
    k_csr_fill<<<(E + 255) / 256, 256>>>(src, dst, rowptr, fill, esrc, E);

    // ---- layer 1: a0 = Âx, z1 = a0@W1 (fused stats -> layer 0) ----
    k_gather9<<<(N + 255) / 256, 256>>>(x, dis, rowptr, esrc, a0, N);
    k_gemm1<<<(N + 31) / 32, 256>>>(a0, W1, hw, N);

    // ---- layer 2: a1 = Â relu(BN0(z1)), z2 = a1@W2 (stats -> layer 1) ----
    k_gather<128><<<(N + 7) / 8, 256>>>(hw, dis, rowptr, esrc, agg, N, 0, gm1, be1);
    {
        dim3 grid(2, (N + 127) / 128);
        k_gemm_mma<true, false><<<grid, 256>>>(agg, W2, hw, N, 128, 256, 256, nullptr);
    }

    // ---- layer 3: a2 = Â relu(BN1(z2)), z3 = a2@W3 (stats -> layer 2) ----
    k_gather<256><<<(2 * N + 7) / 8, 256>>>(hw, dis, rowptr, esrc, agg, N, 256, gm2, be2);
    {
        dim3 grid(2, (N + 127) / 128);
        k_gemm_mma<true, false><<<grid, 256>>>(agg, W3, hw, N, 256, 256, 512, nullptr);
    }

    // ---- pooling over relu(BN2(z3)) ----
    k_pool<<<G, 256>>>(hw, gptr, pm, N, 512, gm3, be3);

    // ---- head: d_out = pm @ Wp + bp (tf32 mma) ----
    {
        dim3 grid(P / 128, (G + 127) / 128);
        k_gemm_mma<false, true><<<grid, 256>>>(pm, Wp, (float*)d_out, G, 256, P, 0, bp);
    }
}

// round 17
// speedup vs baseline: 2.0480x; 1.0197x over previous
#include <cuda_runtime.h>
#include <stdint.h>

#define NMAX 200000
#define EMAX 400000
#define GMAX 8192
#define HMAX 256
#define BN_EPS 1e-5f

// ---------------- scratch (device globals: no allocation allowed) ----------
__device__ float g_dis[NMAX];
__device__ float g_hw[(size_t)NMAX * HMAX];
__device__ float g_agg[(size_t)NMAX * HMAX];
__device__ float g_a0[(size_t)NMAX * 9];
__device__ float g_colsum[3 * 256];
__device__ float g_colsumsq[3 * 256];
__device__ float g_pm[(size_t)GMAX * HMAX];
__device__ int g_rowcnt[NMAX];
__device__ int g_rowptr[NMAX + 1];
__device__ int g_fill[NMAX];
__device__ int g_esrc[EMAX];
__device__ int g_gcnt[GMAX];
__device__ int g_gptr[GMAX + 1];
__device__ int g_bsum[1024];
__device__ int g_boff[1024];

// ---------------- fused setup --------------------------------------------------
__global__ void k_setup(int* rowcnt, int* fill, int* gcnt, int N, int G) {
    int i = blockIdx.x * blockDim.x + threadIdx.x;
    if (i < N) { rowcnt[i] = 0; fill[i] = 0; }
    if (i < G) gcnt[i] = 0;
    if (i < 3 * 256) { g_colsum[i] = 0.f; g_colsumsq[i] = 0.f; }
}

__global__ void k_count2(const int* __restrict__ dst, const int* __restrict__ batch,
                         int* __restrict__ rowcnt, int* __restrict__ gcnt, int E, int N) {
    int i = blockIdx.x * blockDim.x + threadIdx.x;
    if (i < E) atomicAdd(&rowcnt[dst[i]], 1);
    if (i < N) atomicAdd(&gcnt[batch[i]], 1);
}

// ---------------- scan core (1024 elems/block) ---------------------------------
__device__ __forceinline__ void scan_block(const int* __restrict__ in, int n,
                                           int* __restrict__ out, int* __restrict__ bsum,
                                           int blk) {
    __shared__ int sh[256];
    int t = threadIdx.x;
    int base = blk * 1024 + t * 4;
    int v0 = (base + 0 < n) ? in[base + 0] : 0;
    int v1 = (base + 1 < n) ? in[base + 1] : 0;
    int v2 = (base + 2 < n) ? in[base + 2] : 0;
    int v3 = (base + 3 < n) ? in[base + 3] : 0;
    int s = v0 + v1 + v2 + v3;
    sh[t] = s;
    __syncthreads();
    for (int off = 1; off < 256; off <<= 1) {
        int x = (t >= off) ? sh[t - off] : 0;
        __syncthreads();
        sh[t] += x;
        __syncthreads();
    }
    int run = sh[t] - s;
    if (base + 0 < n) out[base + 0] = run; run += v0;
    if (base + 1 < n) out[base + 1] = run; run += v1;
    if (base + 2 < n) out[base + 2] = run; run += v2;
    if (base + 3 < n) out[base + 3] = run;
    if (t == 0) bsum[blk] = sh[255];
}

__global__ void k_scan1_dual(const int* __restrict__ rowcnt, int N,
                             const int* __restrict__ gcnt, int G, int nbN) {
    int b = blockIdx.x;
    if (b < nbN) scan_block(rowcnt, N, g_rowptr, g_bsum, b);
    else scan_block(gcnt, G, g_gptr, g_bsum + 512, b - nbN);
}

__global__ void k_scan2(int nbN, int nbG) {
    __shared__ int dummy;
    int* d = &dummy;
    if (blockIdx.x == 0) scan_block(g_bsum, nbN, g_boff, d, 0);
    else scan_block(g_bsum + 512, nbG, g_boff + 512, d, 0);
}

__global__ void k_scan_add_dual(int* __restrict__ rowptr, int* __restrict__ gptr,
                                const int* __restrict__ rowcnt,
                                float* __restrict__ dis, int N, int G, int E) {
    int i = blockIdx.x * blockDim.x + threadIdx.x;
    if (i < N) {
        rowptr[i] += g_boff[i >> 10];
        dis[i] = rsqrtf((float)rowcnt[i] + 1.0f);
    }
    if (i < G) gptr[i] += g_boff[512 + (i >> 10)];
    if (i == 0) { rowptr[N] = E; gptr[G] = N; }
}

// ---------------- CSR fill ------------------------------------------------------
__global__ void k_csr_fill(const int* __restrict__ src, const int* __restrict__ dst,
                           const int* __restrict__ rowptr, int* __restrict__ fill,
                           int* __restrict__ esrc, int E) {
    int e = blockIdx.x * blockDim.x + threadIdx.x;
    if (e < E) {
        int d = dst[e];
        int pos = rowptr[d] + atomicAdd(&fill[d], 1);
        esrc[pos] = src[e];
    }
}

// ---------------- width-9 gather ------------------------------------------------
__global__ void k_gather9(const float* __restrict__ x, const float* __restrict__ dis,
                          const int* __restrict__ rowptr, const int* __restrict__ esrc,
                          float* __restrict__ out, int N) {
    int n = blockIdx.x * blockDim.x + threadIdx.x;
    if (n >= N) return;
    float dd = dis[n];
    float a[9];
#pragma unroll
    for (int f = 0; f < 9; f++) a[f] = dd * x[(size_t)n * 9 + f];
    int e0 = rowptr[n], e1 = rowptr[n + 1];
    for (int e = e0; e < e1; e++) {
        int s = esrc[e];
        float w = dis[s];
#pragma unroll
        for (int f = 0; f < 9; f++) a[f] += w * x[(size_t)s * 9 + f];
    }
#pragma unroll
    for (int f = 0; f < 9; f++) out[(size_t)n * 9 + f] = dd * a[f];
}

// ---------------- layer-1 GEMM (fused stats) ------------------------------------
__global__ void __launch_bounds__(256)
k_gemm1(const float* __restrict__ x, const float* __restrict__ W,
        float* __restrict__ out, int N) {
    __shared__ float Ws[9 * 128];
    __shared__ float xs[32 * 9];
    __shared__ float red[2][8][128];
    int tid = threadIdx.x;
    for (int i = tid; i < 9 * 128; i += 256) Ws[i] = W[i];
    int r0 = blockIdx.x * 32;
    for (int i = tid; i < 32 * 9; i += 256) {
        int rr = i / 9, cc = i % 9;
        int r = r0 + rr;
        xs[i] = (r < N) ? x[(size_t)r * 9 + cc] : 0.0f;
    }
    __syncthreads();
    int lr = tid >> 5;
    int c4 = (tid & 31) * 4;
    float s[4] = {0.f, 0.f, 0.f, 0.f}, q[4] = {0.f, 0.f, 0.f, 0.f};
#pragma unroll
    for (int i = 0; i < 4; i++) {
        int rr = lr * 4 + i;
        int r = r0 + rr;
        float a0 = 0.f, a1 = 0.f, a2 = 0.f, a3 = 0.f;
#pragma unroll
        for (int k = 0; k < 9; k++) {
            float xv = xs[rr * 9 + k];
            const float* w = &Ws[k * 128 + c4];
            a0 += xv * w[0]; a1 += xv * w[1]; a2 += xv * w[2]; a3 += xv * w[3];
        }
        if (r < N) {
            *(float4*)&out[(size_t)r * 128 + c4] = make_float4(a0, a1, a2, a3);
            s[0] += a0; s[1] += a1; s[2] += a2; s[3] += a3;
            q[0] += a0 * a0; q[1] += a1 * a1; q[2] += a2 * a2; q[3] += a3 * a3;
        }
    }
#pragma unroll
    for (int j = 0; j < 4; j++) { red[0][lr][c4 + j] = s[j]; red[1][lr][c4 + j] = q[j]; }
    __syncthreads();
    if (lr == 0) {
#pragma unroll
        for (int j = 0; j < 4; j++) {
            float ts = 0.f, tq = 0.f;
#pragma unroll
            for (int l = 0; l < 8; l++) { ts += red[0][l][c4 + j]; tq += red[1][l][c4 + j]; }
            atomicAdd(&g_colsum[c4 + j], ts);
            atomicAdd(&g_colsumsq[c4 + j], tq);
        }
    }
}

// ================= tf32 mma.sync GEMM (128x128 tile) ============================
__device__ __forceinline__ uint32_t f2tf32(float x) {
    uint32_t u; asm("cvt.rna.tf32.f32 %0, %1;" : "=r"(u) : "f"(x)); return u;
}
__device__ __forceinline__ int swz(int k) { return ((k & 3) << 3) | (k >> 2); }

__device__ __forceinline__ void mma_tf32(float4& c, uint32_t a0, uint32_t a1,
                                         uint32_t a2, uint32_t a3,
                                         uint32_t b0, uint32_t b1) {
    asm volatile(
        "mma.sync.aligned.m16n8k8.row.col.f32.tf32.tf32.f32 "
        "{%0,%1,%2,%3}, {%4,%5,%6,%7}, {%8,%9}, {%0,%1,%2,%3};"
        : "+f"(c.x), "+f"(c.y), "+f"(c.z), "+f"(c.w)
        : "r"(a0), "r"(a1), "r"(a2), "r"(a3), "r"(b0), "r"(b1));
}

template <bool STATS, bool BIAS>
__global__ void __launch_bounds__(256, 1)
k_gemm_mma(const float* __restrict__ A, const float* __restrict__ W,
           float* __restrict__ C, int M, int K, int Nc, int so,
           const float* __restrict__ bias) {
    __shared__ uint32_t As[32 * 128];
    __shared__ uint32_t Bs[32 * 128];
    int tid = threadIdx.x;
    int lane = tid & 31, warp = tid >> 5;
    int g = lane >> 2, tig = lane & 3;
    int wm = warp & 3, wn = warp >> 2;
    int rowBase = blockIdx.y * 128;
    int colBase = blockIdx.x * 128;

    int ar[4], akq[4], bk[4], bn4[4];
#pragma unroll
    for (int l = 0; l < 4; l++) {
        int lin = l * 256 + tid;
        ar[l] = lin >> 3;
        akq[l] = (lin & 7) * 4;
        bk[l] = lin >> 5;
        bn4[l] = (lin & 31) * 4;
    }

    float4 av[4], bv[4];
#pragma unroll
    for (int l = 0; l < 4; l++) {
        int gr = rowBase + ar[l];
        av[l] = make_float4(0.f, 0.f, 0.f, 0.f);
        if (gr < M) av[l] = *(const float4*)&A[(size_t)gr * K + akq[l]];
        bv[l] = *(const float4*)&W[(size_t)bk[l] * Nc + colBase + bn4[l]];
    }

    float4 acc[2][8];
#pragma unroll
    for (int i = 0; i < 2; i++)
#pragma unroll
        for (int j = 0; j < 8; j++) acc[i][j] = make_float4(0.f, 0.f, 0.f, 0.f);

    int nk = K >> 5;
    for (int kc = 0; kc < nk; kc++) {
#pragma unroll
        for (int l = 0; l < 4; l++) {
            int r = ar[l], kq = akq[l];
            As[(kq + 0) * 128 + (r ^ swz(kq + 0))] = f2tf32(av[l].x);
            As[(kq + 1) * 128 + (r ^ swz(kq + 1))] = f2tf32(av[l].y);
            As[(kq + 2) * 128 + (r ^ swz(kq + 2))] = f2tf32(av[l].z);
            As[(kq + 3) * 128 + (r ^ swz(kq + 3))] = f2tf32(av[l].w);
            int k = bk[l], n4 = bn4[l];
            int xk = swz(k);
            Bs[k * 128 + ((n4 + 0) ^ xk)] = f2tf32(bv[l].x);
            Bs[k * 128 + ((n4 + 1) ^ xk)] = f2tf32(bv[l].y);
            Bs[k * 128 + ((n4 + 2) ^ xk)] = f2tf32(bv[l].z);
            Bs[k * 128 + ((n4 + 3) ^ xk)] = f2tf32(bv[l].w);
        }
        __syncthreads();
        if (kc + 1 < nk) {
            int k0 = (kc + 1) * 32;
#pragma unroll
            for (int l = 0; l < 4; l++) {
                int gr = rowBase + ar[l];
                av[l] = make_float4(0.f, 0.f, 0.f, 0.f);
                if (gr < M) av[l] = *(const float4*)&A[(size_t)gr * K + k0 + akq[l]];
                bv[l] = *(const float4*)&W[(size_t)(k0 + bk[l]) * Nc + colBase + bn4[l]];
            }
        }
#pragma unroll
        for (int s = 0; s < 4; s++) {
            int kA = s * 8 + tig;
            int kB = kA + 4;
            int xa = swz(kA), xb = swz(kB);
            uint32_t a[2][4];
#pragma unroll
            for (int mt = 0; mt < 2; mt++) {
                int m = wm * 32 + mt * 16 + g;
                a[mt][0] = As[kA * 128 + (m ^ xa)];
                a[mt][1] = As[kA * 128 + ((m + 8) ^ xa)];
                a[mt][2] = As[kB * 128 + (m ^ xb)];
                a[mt][3] = As[kB * 128 + ((m + 8) ^ xb)];
            }
#pragma unroll
            for (int nt = 0; nt < 8; nt++) {
                int n = wn * 64 + nt * 8 + g;
                uint32_t b0 = Bs[kA * 128 + (n ^ xa)];
                uint32_t b1 = Bs[kB * 128 + (n ^ xb)];
                mma_tf32(acc[0][nt], a[0][0], a[0][1], a[0][2], a[0][3], b0, b1);
                mma_tf32(acc[1][nt], a[1][0], a[1][1], a[1][2], a[1][3], b0, b1);
            }
        }
        __syncthreads();
    }
#pragma unroll
    for (int mt = 0; mt < 2; mt++) {
        int r0 = rowBase + wm * 32 + mt * 16 + g;
#pragma unroll
        for (int nt = 0; nt < 8; nt++) {
            int c = colBase + wn * 64 + nt * 8 + tig * 2;
            float2 v0 = make_float2(acc[mt][nt].x, acc[mt][nt].y);
            float2 v1 = make_float2(acc[mt][nt].z, acc[mt][nt].w);
            if (BIAS) {
                v0.x += bias[c]; v0.y += bias[c + 1];
                v1.x += bias[c]; v1.y += bias[c + 1];
            }
            if (r0 < M) *(float2*)&C[(size_t)r0 * Nc + c] = v0;
            if (r0 + 8 < M) *(float2*)&C[(size_t)(r0 + 8) * Nc + c] = v1;
        }
    }
    if (STATS) {
#pragma unroll
        for (int nt = 0; nt < 8; nt++) {
            float4 u = acc[0][nt], v = acc[1][nt];
            float s0 = u.x + u.z + v.x + v.z;
            float s1 = u.y + u.w + v.y + v.w;
            float q0 = u.x * u.x + u.z * u.z + v.x * v.x + v.z * v.z;
            float q1 = u.y * u.y + u.w * u.w + v.y * v.y + v.w * v.w;
#pragma unroll
            for (int off = 4; off < 32; off <<= 1) {
                s0 += __shfl_xor_sync(0xffffffffu, s0, off);
                s1 += __shfl_xor_sync(0xffffffffu, s1, off);
                q0 += __shfl_xor_sync(0xffffffffu, q0, off);
                q1 += __shfl_xor_sync(0xffffffffu, q1, off);
            }
            if (lane < 4) {
                int c = colBase + wn * 64 + nt * 8 + lane * 2;
                atomicAdd(&g_colsum[so + c], s0);
                atomicAdd(&g_colsum[so + c + 1], s1);
                atomicAdd(&g_colsumsq[so + c], q0);
                atomicAdd(&g_colsumsq[so + c + 1], q1);
            }
        }
    }
}

// ---------------- BN helper ----------------------------------------------------
__device__ __forceinline__ float4 bn_relu4(float4 x, float4 sc, float4 sh) {
    x.x = fmaxf(x.x * sc.x + sh.x, 0.f);
    x.y = fmaxf(x.y * sc.y + sh.y, 0.f);
    x.z = fmaxf(x.z * sc.z + sh.z, 0.f);
    x.w = fmaxf(x.w * sc.w + sh.w, 0.f);
    return x;
}

// ---------------- gather width 128: TWO nodes per warp (interleaved) ------------
__global__ void __launch_bounds__(256)
k_gather128(const float* __restrict__ hw, const float* __restrict__ dis,
            const int* __restrict__ rowptr, const int* __restrict__ esrc,
            float* __restrict__ agg, int N, int so,
            const float* __restrict__ gam, const float* __restrict__ bet) {
    __shared__ __align__(16) float s_sc[128];
    __shared__ __align__(16) float s_sh[128];
    int tid = threadIdx.x;
    if (tid < 128) {
        float inv = 1.0f / (float)N;
        float mean = g_colsum[so + tid] * inv;
        float var = fmaxf(g_colsumsq[so + tid] * inv - mean * mean, 0.f);
        float sc = gam[tid] * rsqrtf(var + BN_EPS);
        s_sc[tid] = sc;
        s_sh[tid] = bet[tid] - mean * sc;
    }
    __syncthreads();

    int w = (blockIdx.x * blockDim.x + tid) >> 5;
    int lane = tid & 31;
    int nA = 2 * w, nB = 2 * w + 1;
    if (nA >= N) return;
    bool hasB = nB < N;
    int c = lane * 4;

    float4 sc = *(const float4*)&s_sc[c];
    float4 sh = *(const float4*)&s_sh[c];

    int e0a = __ldg(&rowptr[nA]), e1a = __ldg(&rowptr[nA + 1]);
    float dda = __ldg(&dis[nA]);
    int e0b = 0, e1b = 0; float ddb = 0.f;
    if (hasB) { e0b = __ldg(&rowptr[nB]); e1b = __ldg(&rowptr[nB + 1]); ddb = __ldg(&dis[nB]); }

    float4 accA = make_float4(0.f, 0.f, 0.f, 0.f);
    float4 accB = make_float4(0.f, 0.f, 0.f, 0.f);
    int ia = e0a, ib = e0b;
    // interleaved: 2 independent chains per iteration
    while (ia < e1a && ib < e1b) {
        int sa = __ldg(&esrc[ia]);
        int sb = __ldg(&esrc[ib]);
        float wa = __ldg(&dis[sa]);
        float wb = __ldg(&dis[sb]);
        float4 xa = bn_relu4(__ldg((const float4*)&hw[(size_t)sa * 128 + c]), sc, sh);
        float4 xb = bn_relu4(__ldg((const float4*)&hw[(size_t)sb * 128 + c]), sc, sh);
        accA.x += wa * xa.x; accA.y += wa * xa.y; accA.z += wa * xa.z; accA.w += wa * xa.w;
        accB.x += wb * xb.x; accB.y += wb * xb.y; accB.z += wb * xb.z; accB.w += wb * xb.w;
        ia++; ib++;
    }
    for (; ia < e1a; ia++) {
        int sa = __ldg(&esrc[ia]);
        float wa = __ldg(&dis[sa]);
        float4 xa = bn_relu4(__ldg((const float4*)&hw[(size_t)sa * 128 + c]), sc, sh);
        accA.x += wa * xa.x; accA.y += wa * xa.y; accA.z += wa * xa.z; accA.w += wa * xa.w;
    }
    for (; ib < e1b; ib++) {
        int sb = __ldg(&esrc[ib]);
        float wb = __ldg(&dis[sb]);
        float4 xb = bn_relu4(__ldg((const float4*)&hw[(size_t)sb * 128 + c]), sc, sh);
        accB.x += wb * xb.x; accB.y += wb * xb.y; accB.z += wb * xb.z; accB.w += wb * xb.w;
    }
    {
        float4 xa = bn_relu4(__ldg((const float4*)&hw[(size_t)nA * 128 + c]), sc, sh);
        float4 r;
        r.x = dda * (accA.x + dda * xa.x);
        r.y = dda * (accA.y + dda * xa.y);
        r.z = dda * (accA.z + dda * xa.z);
        r.w = dda * (accA.w + dda * xa.w);
        *(float4*)&agg[(size_t)nA * 128 + c] = r;
    }
    if (hasB) {
        float4 xb = bn_relu4(__ldg((const float4*)&hw[(size_t)nB * 128 + c]), sc, sh);
        float4 r;
        r.x = ddb * (accB.x + ddb * xb.x);
        r.y = ddb * (accB.y + ddb * xb.y);
        r.z = ddb * (accB.z + ddb * xb.z);
        r.w = ddb * (accB.w + ddb * xb.w);
        *(float4*)&agg[(size_t)nB * 128 + c] = r;
    }
}

// ---------------- gather width 256: one warp/node, 2 float4/lane ----------------
__global__ void __launch_bounds__(256)
k_gather256(const float* __restrict__ hw, const float* __restrict__ dis,
            const int* __restrict__ rowptr, const int* __restrict__ esrc,
            float* __restrict__ agg, int N, int so,
            const float* __restrict__ gam, const float* __restrict__ bet) {
    __shared__ __align__(16) float s_sc[256];
    __shared__ __align__(16) float s_sh[256];
    int tid = threadIdx.x;
    {
        float inv = 1.0f / (float)N;
        float mean = g_colsum[so + tid] * inv;
        float var = fmaxf(g_colsumsq[so + tid] * inv - mean * mean, 0.f);
        float sc = gam[tid] * rsqrtf(var + BN_EPS);
        s_sc[tid] = sc;
        s_sh[tid] = bet[tid] - mean * sc;
    }
    __syncthreads();

    int n = (blockIdx.x * blockDim.x + tid) >> 5;
    int lane = tid & 31;
    if (n >= N) return;
    int c = lane * 4;

    float4 sc0 = *(const float4*)&s_sc[c];
    float4 sh0 = *(const float4*)&s_sh[c];
    float4 sc1 = *(const float4*)&s_sc[c + 128];
    float4 sh1 = *(const float4*)&s_sh[c + 128];

    int e0 = __ldg(&rowptr[n]), e1 = __ldg(&rowptr[n + 1]);
    float dd = __ldg(&dis[n]);

    float4 acc0 = make_float4(0.f, 0.f, 0.f, 0.f);
    float4 acc1 = make_float4(0.f, 0.f, 0.f, 0.f);
    int s_nxt = 0; float w_nxt = 0.f;
    if (e0 < e1) { s_nxt = __ldg(&esrc[e0]); w_nxt = __ldg(&dis[s_nxt]); }
    for (int e = e0; e < e1; e++) {
        int s = s_nxt; float ws = w_nxt;
        if (e + 1 < e1) { s_nxt = __ldg(&esrc[e + 1]); w_nxt = __ldg(&dis[s_nxt]); }
        const float* row = &hw[(size_t)s * 256 + c];
        float4 x0 = bn_relu4(__ldg((const float4*)row), sc0, sh0);
        float4 x1 = bn_relu4(__ldg((const float4*)(row + 128)), sc1, sh1);
        acc0.x += ws * x0.x; acc0.y += ws * x0.y; acc0.z += ws * x0.z; acc0.w += ws * x0.w;
        acc1.x += ws * x1.x; acc1.y += ws * x1.y; acc1.z += ws * x1.z; acc1.w += ws * x1.w;
    }
    const float* self = &hw[(size_t)n * 256 + c];
    float4 x0 = bn_relu4(__ldg((const float4*)self), sc0, sh0);
    float4 x1 = bn_relu4(__ldg((const float4*)(self + 128)), sc1, sh1);
    float4 r0, r1;
    r0.x = dd * (acc0.x + dd * x0.x); r0.y = dd * (acc0.y + dd * x0.y);
    r0.z = dd * (acc0.z + dd * x0.z); r0.w = dd * (acc0.w + dd * x0.w);
    r1.x = dd * (acc1.x + dd * x1.x); r1.y = dd * (acc1.y + dd * x1.y);
    r1.z = dd * (acc1.z + dd * x1.z); r1.w = dd * (acc1.w + dd * x1.w);
    float* outp = &agg[(size_t)n * 256 + c];
    *(float4*)outp = r0;
    *(float4*)(outp + 128) = r1;
}

// ---------------- pooling: warp per (graph, 128-col slice) ----------------------
__global__ void __launch_bounds__(256)
k_pool(const float* __restrict__ z, const int* __restrict__ gptr,
       float* __restrict__ pm, int N, int G, int so,
       const float* __restrict__ gam, const float* __restrict__ bet) {
    int w = (blockIdx.x * blockDim.x + threadIdx.x) >> 5;
    int lane = threadIdx.x & 31;
    int g = w >> 1, sl = w & 1;
    if (g >= G) return;
    int c = sl * 128 + lane * 4;

    float4 cs = *(const float4*)&g_colsum[so + c];
    float4 cq = *(const float4*)&g_colsumsq[so + c];
    float4 gm4 = __ldg((const float4*)&gam[c]);
    float4 bt4 = __ldg((const float4*)&bet[c]);
    float inv = 1.0f / (float)N;
    float4 sc, sh;
    {
        float m0 = cs.x * inv, m1 = cs.y * inv, m2 = cs.z * inv, m3 = cs.w * inv;
        sc.x = gm4.x * rsqrtf(fmaxf(cq.x * inv - m0 * m0, 0.f) + BN_EPS);
        sc.y = gm4.y * rsqrtf(fmaxf(cq.y * inv - m1 * m1, 0.f) + BN_EPS);
        sc.z = gm4.z * rsqrtf(fmaxf(cq.z * inv - m2 * m2, 0.f) + BN_EPS);
        sc.w = gm4.w * rsqrtf(fmaxf(cq.w * inv - m3 * m3, 0.f) + BN_EPS);
        sh.x = bt4.x - m0 * sc.x; sh.y = bt4.y - m1 * sc.y;
        sh.z = bt4.z - m2 * sc.z; sh.w = bt4.w - m3 * sc.w;
    }
    int r0 = __ldg(&gptr[g]), r1 = __ldg(&gptr[g + 1]);
    float4 s0 = make_float4(0.f, 0.f, 0.f, 0.f);
    float4 s1 = make_float4(0.f, 0.f, 0.f, 0.f);
    int r = r0;
    for (; r + 1 < r1; r += 2) {
        float4 v0 = bn_relu4(__ldg((const float4*)&z[(size_t)r * 256 + c]), sc, sh);
        float4 v1 = bn_relu4(__ldg((const float4*)&z[(size_t)(r + 1) * 256 + c]), sc, sh);
        s0.x += v0.x; s0.y += v0.y; s0.z += v0.z; s0.w += v0.w;
        s1.x += v1.x; s1.y += v1.y; s1.z += v1.z; s1.w += v1.w;
    }
    if (r < r1) {
        float4 v0 = bn_relu4(__ldg((const float4*)&z[(size_t)r * 256 + c]), sc, sh);
        s0.x += v0.x; s0.y += v0.y; s0.z += v0.z; s0.w += v0.w;
    }
    float icnt = 1.0f / fmaxf((float)(r1 - r0), 1.0f);
    float4 out;
    out.x = (s0.x + s1.x) * icnt; out.y = (s0.y + s1.y) * icnt;
    out.z = (s0.z + s1.z) * icnt; out.w = (s0.w + s1.w) * icnt;
    *(float4*)&pm[(size_t)g * 256 + c] = out;
}

// ---------------- host driver ----------------------------------------------------
extern "C" void kernel_launch(void* const* d_in, const int* in_sizes, int n_in,
                              void* d_out, int out_size) {
    const float* x = (const float*)d_in[0];
    const int* ei = (const int*)d_in[1];
    const int* batch = (const int*)d_in[2];
    int o = (in_sizes[3] == 1) ? 4 : 3;
    const float* W1 = (const float*)d_in[o + 0];
    const float* gm1 = (const float*)d_in[o + 2];
    const float* be1 = (const float*)d_in[o + 3];
    const float* W2 = (const float*)d_in[o + 4];
    const float* gm2 = (const float*)d_in[o + 6];
    const float* be2 = (const float*)d_in[o + 7];
    const float* W3 = (const float*)d_in[o + 8];
    const float* gm3 = (const float*)d_in[o + 10];
    const float* be3 = (const float*)d_in[o + 11];
    const float* Wp = (const float*)d_in[o + 12];
    const float* bp = (const float*)d_in[o + 13];

    int N = in_sizes[0] / 9;
    int E = in_sizes[1] / 2;
    int P = in_sizes[o + 13];
    int G = out_size / P;

    float *dis, *hw, *agg, *pm, *a0;
    int *rowcnt, *rowptr, *fill, *esrc, *gcnt, *gptr;
    cudaGetSymbolAddress((void**)&dis, g_dis);
    cudaGetSymbolAddress((void**)&hw, g_hw);
    cudaGetSymbolAddress((void**)&agg, g_agg);
    cudaGetSymbolAddress((void**)&a0, g_a0);
    cudaGetSymbolAddress((void**)&pm, g_pm);
    cudaGetSymbolAddress((void**)&rowcnt, g_rowcnt);
    cudaGetSymbolAddress((void**)&rowptr, g_rowptr);
    cudaGetSymbolAddress((void**)&fill, g_fill);
    cudaGetSymbolAddress((void**)&esrc, g_esrc);
    cudaGetSymbolAddress((void**)&gcnt, g_gcnt);
    cudaGetSymbolAddress((void**)&gptr, g_gptr);

    const int* src = ei;
    const int* dst = ei + E;

    int nbN = (N + 1023) / 1024;
    int nbG = (G + 1023) / 1024;

    // ---- prologue ----
    k_setup<<<(N + 255) / 256, 256>>>(rowcnt, fill, gcnt, N, G);
    k_count2<<<(E + 255) / 256, 256>>>(dst, batch, rowcnt, gcnt, E, N);
    k_scan1_dual<<<nbN + nbG, 256>>>(rowcnt, N, gcnt, G, nbN);
    k_scan2<<<2, 256>>>(nbN, nbG);
    k_scan_add_dual<<<(N + 255) / 256, 256>>>(rowptr, gptr, rowcnt, dis, N, G, E);
    k_csr_fill<<<(E + 255) / 256, 256>>>(src, dst, rowptr, fill, esrc, E);

    // ---- layer 1 ----
    k_gather9<<<(N + 255) / 256, 256>>>(x, dis, rowptr, esrc, a0, N);
    k_gemm1<<<(N + 31) / 32, 256>>>(a0, W1, hw, N);

    // ---- layer 2 ----
    k_gather128<<<(N + 15) / 16, 256>>>(hw, dis, rowptr, esrc, agg, N, 0, gm1, be1);
    {
        dim3 grid(2, (N + 127) / 128);
        k_gemm_mma<true, false><<<grid, 256>>>(agg, W2, hw, N, 128, 256, 256, nullptr);
    }

    // ---- layer 3 ----
    k_gather256<<<(N + 7) / 8, 256>>>(hw, dis, rowptr, esrc, agg, N, 256, gm2, be2);
    {
        dim3 grid(2, (N + 127) / 128);
        k_gemm_mma<true, false><<<grid, 256>>>(agg, W3, hw, N, 256, 256, 512, nullptr);
    }

    // ---- pooling ----
    k_pool<<<(2 * G + 7) / 8, 256>>>(hw, gptr, pm, N, G, 512, gm3, be3);

    // ---- head ----
    {
        dim3 grid(P / 128, (G + 127) / 128);
        k_gemm_mma<false, true><<<grid, 256>>>(pm, Wp, (float*)d_out, G, 256, P, 0, bp);
    }
}